// round 10
// baseline (speedup 1.0000x reference)
#include <cuda_runtime.h>
#include <cuda_bf16.h>

#define B_   8
#define S_   2048
#define E_   256
#define H_   4
#define D_   64
#define M_TOT (B_*S_)

// attention tile
#define QT2  32
#define WR2  160              // QT2 + 2*64
#define KS2  68                // K/Q smem stride (words)
#define VS2  161               // V^T smem stride
#define SPS  164               // scores/probs shared stride

typedef unsigned long long u64;

#define TF32(o, x) asm("cvt.rna.tf32.f32 %0, %1;" : "=r"(o) : "f"(x))
#define MMA_TF32(c, a, b) \
    asm("mma.sync.aligned.m16n8k8.row.col.f32.tf32.tf32.f32 " \
        "{%0,%1,%2,%3}, {%4,%5,%6,%7}, {%8,%9}, {%0,%1,%2,%3};" \
        : "+f"((c).x), "+f"((c).y), "+f"((c).z), "+f"((c).w) \
        : "r"((a)[0]), "r"((a)[1]), "r"((a)[2]), "r"((a)[3]), \
          "r"((b)[0]), "r"((b)[1]))

// GEMM tiles: BM=BN=128, BK=64
#define GSTR 68
#define GBUF (128 * GSTR)

// -------- scratch --------
__device__ float g_qkv[3ull * B_ * H_ * S_ * D_];
__device__ float g_attn[(size_t)M_TOT * E_];
__device__ unsigned int g_ctx_u[B_ * E_];
__device__ float g_h1[B_ * 512];
__device__ float g_h2[B_ * 256];

__device__ __forceinline__ unsigned int f2ord(float f) {
    unsigned int u = __float_as_uint(f);
    return (u & 0x80000000u) ? ~u : (u | 0x80000000u);
}
__device__ __forceinline__ float ord2f(unsigned int u) {
    return (u & 0x80000000u) ? __uint_as_float(u & 0x7FFFFFFFu)
                             : __uint_as_float(~u);
}

// ======================================================================
// Kernel 1: fused embed-gather + QKV GEMM, tf32 MMA, BK=64 single buffer.
// Also initializes g_ctx_u (blocks with by==0, bx<8).
// ======================================================================
__global__ void __launch_bounds__(256) qkv_gemm(const int* __restrict__ text,
                                                const float* __restrict__ emb,
                                                const float* __restrict__ W,
                                                const float* __restrict__ bias) {
    extern __shared__ unsigned smem_u[];
    unsigned* As = smem_u;          // [128][GSTR]
    unsigned* Ws = smem_u + GBUF;   // [128][GSTR]
    __shared__ int tok_s[128];

    const int tid = threadIdx.x;
    const int wid = tid >> 5, lane = tid & 31;
    const int wm = wid & 3, wn = wid >> 2;
    const int qr = lane >> 2, qc = lane & 3;
    const int m0 = blockIdx.x * 128, n0 = blockIdx.y * 128;

    if (blockIdx.y == 0 && blockIdx.x < 8)
        g_ctx_u[blockIdx.x * 256 + tid] = 0u;

    if (tid < 128) tok_s[tid] = text[m0 + tid];
    __syncthreads();

    const int row_  = tid & 127;
    const int cbase = (tid >> 7) * 32;
    const float* arow = emb + (size_t)tok_s[row_] * 256;
    const float* wrow = W + (size_t)(n0 + row_) * 256;

    float4 c[2][8] = {};

    for (int kt = 0; kt < 256; kt += 64) {
        if (kt) __syncthreads();
        #pragma unroll
        for (int cc = 0; cc < 8; ++cc) {
            int c4 = cbase + cc * 4;
            float4 av = *(const float4*)&arow[kt + c4];
            unsigned u0,u1,u2,u3;
            TF32(u0, av.x); TF32(u1, av.y); TF32(u2, av.z); TF32(u3, av.w);
            *(uint4*)&As[row_ * GSTR + c4] = make_uint4(u0,u1,u2,u3);
            float4 wv = *(const float4*)&wrow[kt + c4];
            TF32(u0, wv.x); TF32(u1, wv.y); TF32(u2, wv.z); TF32(u3, wv.w);
            *(uint4*)&Ws[row_ * GSTR + c4] = make_uint4(u0,u1,u2,u3);
        }
        __syncthreads();
        #pragma unroll
        for (int ks = 0; ks < 8; ++ks) {
            const int k0 = ks * 8;
            unsigned a[2][4], b[8][2];
            #pragma unroll
            for (int mt = 0; mt < 2; ++mt) {
                int rb = wm * 32 + mt * 16 + qr;
                a[mt][0] = As[(rb    ) * GSTR + k0 + qc];
                a[mt][1] = As[(rb + 8) * GSTR + k0 + qc];
                a[mt][2] = As[(rb    ) * GSTR + k0 + qc + 4];
                a[mt][3] = As[(rb + 8) * GSTR + k0 + qc + 4];
            }
            #pragma unroll
            for (int nt = 0; nt < 8; ++nt) {
                int nb = wn * 64 + nt * 8 + qr;
                b[nt][0] = Ws[nb * GSTR + k0 + qc];
                b[nt][1] = Ws[nb * GSTR + k0 + qc + 4];
            }
            #pragma unroll
            for (int mt = 0; mt < 2; ++mt)
                #pragma unroll
                for (int nt = 0; nt < 8; ++nt)
                    MMA_TF32(c[mt][nt], a[mt], b[nt]);
        }
    }

    #pragma unroll
    for (int nt = 0; nt < 8; ++nt) {
        const int n_g = n0 + wn * 64 + nt * 8 + 2 * qc;
        const int sec = n_g >> 8;
        const int h   = (n_g >> 6) & 3;
        const int d   = n_g & 63;
        const float scale = (sec == 0) ? 0.125f : 1.0f;
        const float b0v = bias[n_g], b1v = bias[n_g + 1];
        #pragma unroll
        for (int mt = 0; mt < 2; ++mt) {
            float4 cc = c[mt][nt];
            int r = wm * 32 + mt * 16 + qr;
            #pragma unroll
            for (int half = 0; half < 2; ++half) {
                int m = m0 + r + half * 8;
                int bb = m >> 11, s = m & 2047;
                float2 o;
                o.x = ((half ? cc.z : cc.x) + b0v) * scale;
                o.y = ((half ? cc.w : cc.y) + b1v) * scale;
                *(float2*)&g_qkv[((((size_t)sec * B_ + bb) * H_ + h) * S_ + s) * 64 + d] = o;
            }
        }
    }
}

// ======================================================================
// Kernel 2: banded attention via tf32 MMA. QT=32, 512 threads, 16 warps.
// P aliases S (per-warp row-disjoint read-then-overwrite).
// ======================================================================
__global__ void __launch_bounds__(512, 2) attn_kernel() {
    extern __shared__ float smem[];
    float* K_s = smem;                  // [160][68]
    float* Q_s = K_s + WR2 * KS2;       // [32][68]
    float* V_s = Q_s + QT2 * KS2;       // [64][161]
    float* S_s = V_s + 64 * VS2;        // [32][164]  (P aliases this)
    unsigned* Ku = (unsigned*)K_s;
    unsigned* Qu = (unsigned*)Q_s;
    unsigned* Vu = (unsigned*)V_s;
    unsigned* Pu = (unsigned*)S_s;

    const int nq = S_ / QT2;            // 64
    const int qt = blockIdx.x % nq;
    const int h  = (blockIdx.x / nq) % H_;
    const int b  = blockIdx.x / (nq * H_);

    const int q0 = qt * QT2;
    const int kstart = q0 - 64;

    const float* qb = g_qkv + ((size_t)(b * H_ + h)) * S_ * 64;
    const float* kb = g_qkv + ((size_t)(B_ * H_) + b * H_ + h) * S_ * 64;
    const float* vb = g_qkv + ((size_t)(2 * B_ * H_) + b * H_ + h) * S_ * 64;

    const int tid = threadIdx.x;
    const int wid = tid >> 5, lane = tid & 31;
    const int qr = lane >> 2, qc = lane & 3;

    // ---- stage K (tf32) and V^T (tf32) ----
    for (int idx = tid; idx < WR2 * 16; idx += 512) {
        int row = idx >> 4, d4 = (idx & 15) * 4;
        int kg = kstart + row;
        bool in = (kg >= 0) && (kg < S_);
        float4 kv = in ? *(const float4*)&kb[(size_t)kg * 64 + d4]
                       : make_float4(0.f,0.f,0.f,0.f);
        unsigned u0,u1,u2,u3;
        TF32(u0, kv.x); TF32(u1, kv.y); TF32(u2, kv.z); TF32(u3, kv.w);
        *(uint4*)&Ku[row * KS2 + d4] = make_uint4(u0,u1,u2,u3);
        float4 vv = in ? *(const float4*)&vb[(size_t)kg * 64 + d4]
                       : make_float4(0.f,0.f,0.f,0.f);
        TF32(u0, vv.x); TF32(u1, vv.y); TF32(u2, vv.z); TF32(u3, vv.w);
        Vu[(d4+0) * VS2 + row] = u0;
        Vu[(d4+1) * VS2 + row] = u1;
        Vu[(d4+2) * VS2 + row] = u2;
        Vu[(d4+3) * VS2 + row] = u3;
    }
    // ---- stage Q (tf32): exactly 512 items ----
    {
        int r = tid >> 4, d4 = (tid & 15) * 4;
        float4 qv = *(const float4*)&qb[(size_t)(q0 + r) * 64 + d4];
        unsigned u0,u1,u2,u3;
        TF32(u0, qv.x); TF32(u1, qv.y); TF32(u2, qv.z); TF32(u3, qv.w);
        *(uint4*)&Qu[r * KS2 + d4] = make_uint4(u0,u1,u2,u3);
    }
    __syncthreads();

    // ---- scores: S[32,160] = Q x K^T. 40 units (2 m-tiles x 20 n-tiles) ----
    for (int u = wid; u < 40; u += 16) {
        const int mt = u / 20, tt = u % 20;
        float4 c = {0.f, 0.f, 0.f, 0.f};
        #pragma unroll
        for (int ks = 0; ks < 8; ++ks) {
            const int k0 = ks * 8;
            unsigned a[4], bf[2];
            a[0] = Qu[(mt * 16 + qr    ) * KS2 + k0 + qc];
            a[1] = Qu[(mt * 16 + qr + 8) * KS2 + k0 + qc];
            a[2] = Qu[(mt * 16 + qr    ) * KS2 + k0 + qc + 4];
            a[3] = Qu[(mt * 16 + qr + 8) * KS2 + k0 + qc + 4];
            bf[0] = Ku[(tt * 8 + qr) * KS2 + k0 + qc];
            bf[1] = Ku[(tt * 8 + qr) * KS2 + k0 + qc + 4];
            MMA_TF32(c, a, bf);
        }
        *(float2*)&S_s[(mt * 16 + qr    ) * SPS + tt * 8 + 2 * qc] = make_float2(c.x, c.y);
        *(float2*)&S_s[(mt * 16 + qr + 8) * SPS + tt * 8 + 2 * qc] = make_float2(c.z, c.w);
    }
    __syncthreads();

    // ---- softmax: warp handles rows 2*wid, 2*wid+1; P overwrites S ----
    #pragma unroll
    for (int rr = 0; rr < 2; ++rr) {
        const int row = wid * 2 + rr;
        float sc[5];
        #pragma unroll
        for (int r = 0; r < 5; ++r) {
            int t = lane + 32 * r;
            int j = row + t;
            int kg = kstart + j;
            bool valid = (t <= 128) && (kg >= 0) && (kg < S_);
            sc[r] = valid ? S_s[row * SPS + j] : -3.0e38f;
        }
        float mx = sc[0];
        #pragma unroll
        for (int r = 1; r < 5; ++r) mx = fmaxf(mx, sc[r]);
        #pragma unroll
        for (int off = 16; off > 0; off >>= 1)
            mx = fmaxf(mx, __shfl_xor_sync(0xffffffffu, mx, off));
        float sum = 0.f;
        #pragma unroll
        for (int r = 0; r < 5; ++r) { sc[r] = __expf(sc[r] - mx); sum += sc[r]; }
        #pragma unroll
        for (int off = 16; off > 0; off >>= 1)
            sum += __shfl_xor_sync(0xffffffffu, sum, off);
        float inv = 1.0f / sum;

        #pragma unroll
        for (int t = lane; t < WR2; t += 32) Pu[row * SPS + t] = 0u;
        __syncwarp();
        #pragma unroll
        for (int r = 0; r < 5; ++r) {
            int t = lane + 32 * r;
            if (t <= 128) {
                float p = sc[r] * inv;
                unsigned u; TF32(u, p);
                Pu[row * SPS + row + t] = u;
            }
        }
        __syncwarp();
    }
    __syncthreads();

    // ---- AV: D[32,64] = P x V. 16 units: warp = (mt, nt) ----
    {
        const int mt = wid >> 3, nt = wid & 7;
        float4 d = {0.f, 0.f, 0.f, 0.f};
        #pragma unroll
        for (int ks = 0; ks < 20; ++ks) {
            const int k0 = ks * 8;
            unsigned a[4], bf[2];
            a[0] = Pu[(mt * 16 + qr    ) * SPS + k0 + qc];
            a[1] = Pu[(mt * 16 + qr + 8) * SPS + k0 + qc];
            a[2] = Pu[(mt * 16 + qr    ) * SPS + k0 + qc + 4];
            a[3] = Pu[(mt * 16 + qr + 8) * SPS + k0 + qc + 4];
            bf[0] = Vu[(nt * 8 + qr) * VS2 + k0 + qc];
            bf[1] = Vu[(nt * 8 + qr) * VS2 + k0 + qc + 4];
            MMA_TF32(d, a, bf);
        }
        const int dim = h * 64 + nt * 8 + 2 * qc;
        int s = q0 + mt * 16 + qr;
        *(float2*)&g_attn[((size_t)(b * S_ + s)) * 256 + dim] = make_float2(d.x, d.y);
        s += 8;
        *(float2*)&g_attn[((size_t)(b * S_ + s)) * 256 + dim] = make_float2(d.z, d.w);
    }
}

// ======================================================================
// Kernel 3: out_proj GEMM (tf32 MMA, BK=64) + fused max-pool.
// ======================================================================
__global__ void __launch_bounds__(256) proj_pool_gemm(const float* __restrict__ W,
                                                      const float* __restrict__ bias) {
    extern __shared__ unsigned smem_u[];
    unsigned* As = smem_u;
    unsigned* Ws = smem_u + GBUF;

    const int tid = threadIdx.x;
    const int wid = tid >> 5, lane = tid & 31;
    const int wm = wid & 3, wn = wid >> 2;
    const int qr = lane >> 2, qc = lane & 3;
    const int m0 = blockIdx.x * 128, n0 = blockIdx.y * 128;

    const int row_  = tid & 127;
    const int cbase = (tid >> 7) * 32;
    const float* arow = g_attn + (size_t)(m0 + row_) * 256;
    const float* wrow = W + (size_t)(n0 + row_) * 256;

    float4 c[2][8] = {};

    for (int kt = 0; kt < 256; kt += 64) {
        if (kt) __syncthreads();
        #pragma unroll
        for (int cc = 0; cc < 8; ++cc) {
            int c4 = cbase + cc * 4;
            float4 av = *(const float4*)&arow[kt + c4];
            unsigned u0,u1,u2,u3;
            TF32(u0, av.x); TF32(u1, av.y); TF32(u2, av.z); TF32(u3, av.w);
            *(uint4*)&As[row_ * GSTR + c4] = make_uint4(u0,u1,u2,u3);
            float4 wv = *(const float4*)&wrow[kt + c4];
            TF32(u0, wv.x); TF32(u1, wv.y); TF32(u2, wv.z); TF32(u3, wv.w);
            *(uint4*)&Ws[row_ * GSTR + c4] = make_uint4(u0,u1,u2,u3);
        }
        __syncthreads();
        #pragma unroll
        for (int ks = 0; ks < 8; ++ks) {
            const int k0 = ks * 8;
            unsigned a[2][4], b[8][2];
            #pragma unroll
            for (int mt = 0; mt < 2; ++mt) {
                int rb = wm * 32 + mt * 16 + qr;
                a[mt][0] = As[(rb    ) * GSTR + k0 + qc];
                a[mt][1] = As[(rb + 8) * GSTR + k0 + qc];
                a[mt][2] = As[(rb    ) * GSTR + k0 + qc + 4];
                a[mt][3] = As[(rb + 8) * GSTR + k0 + qc + 4];
            }
            #pragma unroll
            for (int nt = 0; nt < 8; ++nt) {
                int nb = wn * 64 + nt * 8 + qr;
                b[nt][0] = Ws[nb * GSTR + k0 + qc];
                b[nt][1] = Ws[nb * GSTR + k0 + qc + 4];
            }
            #pragma unroll
            for (int mt = 0; mt < 2; ++mt)
                #pragma unroll
                for (int nt = 0; nt < 8; ++nt)
                    MMA_TF32(c[mt][nt], a[mt], b[nt]);
        }
    }

    float v0[8], v1[8];
    #pragma unroll
    for (int nt = 0; nt < 8; ++nt) {
        v0[nt] = fmaxf(fmaxf(c[0][nt].x, c[0][nt].z), fmaxf(c[1][nt].x, c[1][nt].z));
        v1[nt] = fmaxf(fmaxf(c[0][nt].y, c[0][nt].w), fmaxf(c[1][nt].y, c[1][nt].w));
    }
    #pragma unroll
    for (int off = 4; off <= 16; off <<= 1) {
        #pragma unroll
        for (int nt = 0; nt < 8; ++nt) {
            v0[nt] = fmaxf(v0[nt], __shfl_xor_sync(0xffffffffu, v0[nt], off));
            v1[nt] = fmaxf(v1[nt], __shfl_xor_sync(0xffffffffu, v1[nt], off));
        }
    }
    if (lane < 4) {
        const int bb = m0 >> 11;
        #pragma unroll
        for (int nt = 0; nt < 8; ++nt) {
            int n_g = n0 + wn * 64 + nt * 8 + 2 * lane;
            atomicMax(&g_ctx_u[bb * 256 + n_g],     f2ord(v0[nt] + bias[n_g]));
            atomicMax(&g_ctx_u[bb * 256 + n_g + 1], f2ord(v1[nt] + bias[n_g + 1]));
        }
    }
}

// ======================================================================
// MLP head.
// ======================================================================
__global__ void __launch_bounds__(256) fc1_kernel(const float* __restrict__ w,
                                                  const float* __restrict__ bias) {
    const int gid = blockIdx.x * 8 + (threadIdx.x >> 5);
    const int lane = threadIdx.x & 31;
    const int b = gid >> 9, o = gid & 511;
    const float* wr = w + (size_t)o * 256 + lane * 8;
    const unsigned* xr = g_ctx_u + b * 256 + lane * 8;
    float4 w0 = *(const float4*)wr,  w1 = *(const float4*)(wr + 4);
    uint4 xu0 = *(const uint4*)xr,   xu1 = *(const uint4*)(xr + 4);
    float acc = w0.x*ord2f(xu0.x) + w0.y*ord2f(xu0.y) + w0.z*ord2f(xu0.z) + w0.w*ord2f(xu0.w)
              + w1.x*ord2f(xu1.x) + w1.y*ord2f(xu1.y) + w1.z*ord2f(xu1.z) + w1.w*ord2f(xu1.w);
    #pragma unroll
    for (int off = 16; off > 0; off >>= 1)
        acc += __shfl_xor_sync(0xffffffffu, acc, off);
    if (lane == 0) {
        acc += bias[o];
        g_h1[gid] = acc > 0.f ? acc : 0.01f * acc;
    }
}

__global__ void __launch_bounds__(256) fc2_kernel(const float* __restrict__ w,
                                                  const float* __restrict__ bias) {
    const int gid = blockIdx.x * 8 + (threadIdx.x >> 5);
    const int lane = threadIdx.x & 31;
    const int b = gid >> 8, o = gid & 255;
    const float* wr = w + (size_t)o * 512 + lane * 16;
    const float* xr = g_h1 + b * 512 + lane * 16;
    float acc = 0.f;
    #pragma unroll
    for (int cc = 0; cc < 4; ++cc) {
        float4 wv = *(const float4*)(wr + cc * 4);
        float4 xv = *(const float4*)(xr + cc * 4);
        acc += wv.x*xv.x + wv.y*xv.y + wv.z*xv.z + wv.w*xv.w;
    }
    #pragma unroll
    for (int off = 16; off > 0; off >>= 1)
        acc += __shfl_xor_sync(0xffffffffu, acc, off);
    if (lane == 0) {
        acc += bias[o];
        g_h2[gid] = acc > 0.f ? acc : 0.01f * acc;
    }
}

__global__ void __launch_bounds__(256) fc3_kernel(const float* __restrict__ w,
                                                  const float* __restrict__ bias,
                                                  float* __restrict__ out) {
    const int gid = blockIdx.x * 8 + (threadIdx.x >> 5);
    const int lane = threadIdx.x & 31;
    if (gid >= 8 * 20) return;
    const int b = gid / 20, o = gid % 20;
    const float* wr = w + (size_t)o * 256 + lane * 8;
    const float* xr = g_h2 + b * 256 + lane * 8;
    float4 w0 = *(const float4*)wr,  w1 = *(const float4*)(wr + 4);
    float4 x0 = *(const float4*)xr,  x1 = *(const float4*)(xr + 4);
    float acc = w0.x*x0.x + w0.y*x0.y + w0.z*x0.z + w0.w*x0.w
              + w1.x*x1.x + w1.y*x1.y + w1.z*x1.z + w1.w*x1.w;
    #pragma unroll
    for (int off = 16; off > 0; off >>= 1)
        acc += __shfl_xor_sync(0xffffffffu, acc, off);
    if (lane == 0) out[b * 20 + o] = acc + bias[o];
}

// ======================================================================
extern "C" void kernel_launch(void* const* d_in, const int* in_sizes, int n_in,
                              void* d_out, int out_size) {
    const int*   text = (const int*)d_in[0];
    const float* emb  = (const float*)d_in[1];
    const float* ipw  = (const float*)d_in[2];
    const float* ipb  = (const float*)d_in[3];
    const float* opw  = (const float*)d_in[4];
    const float* opb  = (const float*)d_in[5];
    const float* fc1w = (const float*)d_in[6];
    const float* fc1b = (const float*)d_in[7];
    const float* fc2w = (const float*)d_in[8];
    const float* fc2b = (const float*)d_in[9];
    const float* fc3w = (const float*)d_in[10];
    const float* fc3b = (const float*)d_in[11];
    float* out = (float*)d_out;

    const int gemm_smem = 2 * GBUF * 4;   // 69632 B
    const int attn_smem = (WR2 * KS2 + QT2 * KS2 + 64 * VS2 + QT2 * SPS) * sizeof(float); // 114432 B

    cudaFuncSetAttribute(qkv_gemm, cudaFuncAttributeMaxDynamicSharedMemorySize, gemm_smem);
    qkv_gemm<<<dim3(M_TOT / 128, 6), 256, gemm_smem>>>(text, emb, ipw, ipb);

    cudaFuncSetAttribute(attn_kernel, cudaFuncAttributeMaxDynamicSharedMemorySize, attn_smem);
    attn_kernel<<<B_ * H_ * (S_ / QT2), 512, attn_smem>>>();

    cudaFuncSetAttribute(proj_pool_gemm, cudaFuncAttributeMaxDynamicSharedMemorySize, gemm_smem);
    proj_pool_gemm<<<dim3(M_TOT / 128, 2), 256, gemm_smem>>>(opw, opb);

    fc1_kernel<<<512, 256>>>(fc1w, fc1b);
    fc2_kernel<<<256, 256>>>(fc2w, fc2b);
    fc3_kernel<<<20, 256>>>(fc3w, fc3b, out);
}

// round 11
// speedup vs baseline: 1.0204x; 1.0204x over previous
#include <cuda_runtime.h>
#include <cuda_bf16.h>

#define B_   8
#define S_   2048
#define E_   256
#define H_   4
#define D_   64
#define M_TOT (B_*S_)
#define QT   16
#define WROWS 144
#define KSTR 68
#define VSTR 145
#define SSTR 148
#define PSTR 148

typedef unsigned long long u64;

#define TF32(o, x) asm("cvt.rna.tf32.f32 %0, %1;" : "=r"(o) : "f"(x))
#define MMA_TF32(c, a, b) \
    asm("mma.sync.aligned.m16n8k8.row.col.f32.tf32.tf32.f32 " \
        "{%0,%1,%2,%3}, {%4,%5,%6,%7}, {%8,%9}, {%0,%1,%2,%3};" \
        : "+f"((c).x), "+f"((c).y), "+f"((c).z), "+f"((c).w) \
        : "r"((a)[0]), "r"((a)[1]), "r"((a)[2]), "r"((a)[3]), \
          "r"((b)[0]), "r"((b)[1]))

#define ASTR 36   // GEMM smem stride (words): fragment bank = lane id

// -------- scratch --------
__device__ float g_qkv[3ull * B_ * H_ * S_ * D_];
__device__ float g_attn[(size_t)M_TOT * E_];
__device__ unsigned int g_ctx_u[B_ * E_];
__device__ float g_h1[B_ * 512];
__device__ float g_h2[B_ * 256];

__device__ __forceinline__ unsigned int f2ord(float f) {
    unsigned int u = __float_as_uint(f);
    return (u & 0x80000000u) ? ~u : (u | 0x80000000u);
}
__device__ __forceinline__ float ord2f(unsigned int u) {
    return (u & 0x80000000u) ? __uint_as_float(u & 0x7FFFFFFFu)
                             : __uint_as_float(~u);
}

// ======================================================================
// Kernel 1: fused embed-gather + QKV GEMM via tf32 MMA (R7 body).
// Grid (6, 128): x = n-block, y = m-block => blocks sharing the same
// gathered A tile are co-scheduled (L2 reuse). Also zeroes g_ctx_u.
// ======================================================================
__global__ void __launch_bounds__(256) qkv_gemm(const int* __restrict__ text,
                                                const float* __restrict__ emb,
                                                const float* __restrict__ W,
                                                const float* __restrict__ bias) {
    __shared__ unsigned As[128 * ASTR];
    __shared__ unsigned Ws[128 * ASTR];
    __shared__ int tok_s[128];

    const int tid = threadIdx.x;
    const int wid = tid >> 5, lane = tid & 31;
    const int wm = wid & 3, wn = wid >> 2;
    const int qr = lane >> 2, qc = lane & 3;
    const int m0 = blockIdx.y * 128, n0 = blockIdx.x * 128;

    if (blockIdx.x == 0 && blockIdx.y < 8)
        g_ctx_u[blockIdx.y * 256 + tid] = 0u;

    if (tid < 128) tok_s[tid] = text[m0 + tid];

    float4 c[2][8] = {};

    for (int kt = 0; kt < 256; kt += 32) {
        __syncthreads();
        #pragma unroll
        for (int it = 0; it < 4; ++it) {
            int idx = tid + it * 256;
            int row = idx >> 3;
            int c4  = (idx & 7) * 4;
            float4 av = *(const float4*)&emb[(size_t)tok_s[row] * 256 + kt + c4];
            unsigned u0,u1,u2,u3;
            TF32(u0, av.x); TF32(u1, av.y); TF32(u2, av.z); TF32(u3, av.w);
            *(uint4*)&As[row * ASTR + c4] = make_uint4(u0,u1,u2,u3);
            float4 wv = *(const float4*)&W[(size_t)(n0 + row) * 256 + kt + c4];
            TF32(u0, wv.x); TF32(u1, wv.y); TF32(u2, wv.z); TF32(u3, wv.w);
            *(uint4*)&Ws[row * ASTR + c4] = make_uint4(u0,u1,u2,u3);
        }
        __syncthreads();
        #pragma unroll
        for (int ks = 0; ks < 4; ++ks) {
            const int k0 = ks * 8;
            unsigned a[2][4], b[8][2];
            #pragma unroll
            for (int mt = 0; mt < 2; ++mt) {
                int rb = wm * 32 + mt * 16 + qr;
                a[mt][0] = As[(rb    ) * ASTR + k0 + qc];
                a[mt][1] = As[(rb + 8) * ASTR + k0 + qc];
                a[mt][2] = As[(rb    ) * ASTR + k0 + qc + 4];
                a[mt][3] = As[(rb + 8) * ASTR + k0 + qc + 4];
            }
            #pragma unroll
            for (int nt = 0; nt < 8; ++nt) {
                int nb = wn * 64 + nt * 8 + qr;
                b[nt][0] = Ws[nb * ASTR + k0 + qc];
                b[nt][1] = Ws[nb * ASTR + k0 + qc + 4];
            }
            #pragma unroll
            for (int mt = 0; mt < 2; ++mt)
                #pragma unroll
                for (int nt = 0; nt < 8; ++nt)
                    MMA_TF32(c[mt][nt], a[mt], b[nt]);
        }
    }

    #pragma unroll
    for (int nt = 0; nt < 8; ++nt) {
        const int n_g = n0 + wn * 64 + nt * 8 + 2 * qc;
        const int sec = n_g >> 8;
        const int h   = (n_g >> 6) & 3;
        const int d   = n_g & 63;
        const float scale = (sec == 0) ? 0.125f : 1.0f;
        const float b0v = bias[n_g], b1v = bias[n_g + 1];
        #pragma unroll
        for (int mt = 0; mt < 2; ++mt) {
            float4 cc = c[mt][nt];
            int r = wm * 32 + mt * 16 + qr;
            #pragma unroll
            for (int half = 0; half < 2; ++half) {
                int m = m0 + r + half * 8;
                int bb = m >> 11, s = m & 2047;
                float2 o;
                o.x = ((half ? cc.z : cc.x) + b0v) * scale;
                o.y = ((half ? cc.w : cc.y) + b1v) * scale;
                *(float2*)&g_qkv[((((size_t)sec * B_ + bb) * H_ + h) * S_ + s) * 64 + d] = o;
            }
        }
    }
}

// ======================================================================
// Kernel 2: banded attention via tf32 MMA (identical to R7).
// ======================================================================
__global__ void __launch_bounds__(256) attn_kernel() {
    extern __shared__ float smem[];
    float* K_s = smem;
    float* Q_s = K_s + WROWS * KSTR;
    float* V_s = Q_s + QT * KSTR;
    float* S_s = V_s + 64 * VSTR;
    float* P_s = S_s + QT * SSTR;
    unsigned* Ku = (unsigned*)K_s;
    unsigned* Qu = (unsigned*)Q_s;
    unsigned* Vu = (unsigned*)V_s;
    unsigned* Pu = (unsigned*)P_s;

    const int nq = S_ / QT;
    const int qt = blockIdx.x % nq;
    const int h  = (blockIdx.x / nq) % H_;
    const int b  = blockIdx.x / (nq * H_);

    const int q0 = qt * QT;
    const int kstart = q0 - 64;

    const float* qb = g_qkv + ((size_t)(b * H_ + h)) * S_ * 64;
    const float* kb = g_qkv + ((size_t)(B_ * H_) + b * H_ + h) * S_ * 64;
    const float* vb = g_qkv + ((size_t)(2 * B_ * H_) + b * H_ + h) * S_ * 64;

    const int tid = threadIdx.x;
    const int wid = tid >> 5, lane = tid & 31;
    const int qr = lane >> 2, qc = lane & 3;

    for (int idx = tid; idx < WROWS * 16; idx += 256) {
        int row = idx >> 4, d4 = (idx & 15) * 4;
        int kg = kstart + row;
        bool in = (kg >= 0) && (kg < S_);
        float4 kv = in ? *(const float4*)&kb[(size_t)kg * 64 + d4]
                       : make_float4(0.f,0.f,0.f,0.f);
        unsigned u0,u1,u2,u3;
        TF32(u0, kv.x); TF32(u1, kv.y); TF32(u2, kv.z); TF32(u3, kv.w);
        *(uint4*)&Ku[row * KSTR + d4] = make_uint4(u0,u1,u2,u3);
        float4 vv = in ? *(const float4*)&vb[(size_t)kg * 64 + d4]
                       : make_float4(0.f,0.f,0.f,0.f);
        TF32(u0, vv.x); TF32(u1, vv.y); TF32(u2, vv.z); TF32(u3, vv.w);
        Vu[(d4+0) * VSTR + row] = u0;
        Vu[(d4+1) * VSTR + row] = u1;
        Vu[(d4+2) * VSTR + row] = u2;
        Vu[(d4+3) * VSTR + row] = u3;
    }
    if (tid < QT * 16) {
        int r = tid >> 4, d4 = (tid & 15) * 4;
        float4 qv = *(const float4*)&qb[(size_t)(q0 + r) * 64 + d4];
        unsigned u0,u1,u2,u3;
        TF32(u0, qv.x); TF32(u1, qv.y); TF32(u2, qv.z); TF32(u3, qv.w);
        *(uint4*)&Qu[r * KSTR + d4] = make_uint4(u0,u1,u2,u3);
    }
    __syncthreads();

    for (int tt = wid; tt < 18; tt += 8) {
        float4 c = {0.f, 0.f, 0.f, 0.f};
        #pragma unroll
        for (int ks = 0; ks < 8; ++ks) {
            const int k0 = ks * 8;
            unsigned a[4], bf[2];
            a[0] = Qu[qr * KSTR + k0 + qc];
            a[1] = Qu[(qr + 8) * KSTR + k0 + qc];
            a[2] = Qu[qr * KSTR + k0 + qc + 4];
            a[3] = Qu[(qr + 8) * KSTR + k0 + qc + 4];
            bf[0] = Ku[(tt * 8 + qr) * KSTR + k0 + qc];
            bf[1] = Ku[(tt * 8 + qr) * KSTR + k0 + qc + 4];
            MMA_TF32(c, a, bf);
        }
        *(float2*)&S_s[qr * SSTR + tt * 8 + 2 * qc]       = make_float2(c.x, c.y);
        *(float2*)&S_s[(qr + 8) * SSTR + tt * 8 + 2 * qc] = make_float2(c.z, c.w);
    }
    __syncthreads();

    #pragma unroll
    for (int rr = 0; rr < 2; ++rr) {
        const int row = wid * 2 + rr;
        float sc[5];
        #pragma unroll
        for (int r = 0; r < 5; ++r) {
            int t = lane + 32 * r;
            int j = row + t;
            int kg = kstart + j;
            bool valid = (t <= 128) && (kg >= 0) && (kg < S_);
            sc[r] = valid ? S_s[row * SSTR + j] : -3.0e38f;
        }
        float mx = sc[0];
        #pragma unroll
        for (int r = 1; r < 5; ++r) mx = fmaxf(mx, sc[r]);
        #pragma unroll
        for (int off = 16; off > 0; off >>= 1)
            mx = fmaxf(mx, __shfl_xor_sync(0xffffffffu, mx, off));
        float sum = 0.f;
        #pragma unroll
        for (int r = 0; r < 5; ++r) { sc[r] = __expf(sc[r] - mx); sum += sc[r]; }
        #pragma unroll
        for (int off = 16; off > 0; off >>= 1)
            sum += __shfl_xor_sync(0xffffffffu, sum, off);
        float inv = 1.0f / sum;

        #pragma unroll
        for (int t = lane; t < WROWS; t += 32) Pu[row * PSTR + t] = 0u;
        __syncwarp();
        #pragma unroll
        for (int r = 0; r < 5; ++r) {
            int t = lane + 32 * r;
            if (t <= 128) {
                float p = sc[r] * inv;
                unsigned u; TF32(u, p);
                Pu[row * PSTR + row + t] = u;
            }
        }
        __syncwarp();
    }
    __syncthreads();

    float4 d = {0.f, 0.f, 0.f, 0.f};
    #pragma unroll
    for (int ks = 0; ks < 18; ++ks) {
        const int k0 = ks * 8;
        unsigned a[4], bf[2];
        a[0] = Pu[qr * PSTR + k0 + qc];
        a[1] = Pu[(qr + 8) * PSTR + k0 + qc];
        a[2] = Pu[qr * PSTR + k0 + qc + 4];
        a[3] = Pu[(qr + 8) * PSTR + k0 + qc + 4];
        bf[0] = Vu[(wid * 8 + qr) * VSTR + k0 + qc];
        bf[1] = Vu[(wid * 8 + qr) * VSTR + k0 + qc + 4];
        MMA_TF32(d, a, bf);
    }
    const int dim = h * 64 + wid * 8 + 2 * qc;
    {
        int s = q0 + qr;
        *(float2*)&g_attn[((size_t)(b * S_ + s)) * 256 + dim] = make_float2(d.x, d.y);
        s = q0 + qr + 8;
        *(float2*)&g_attn[((size_t)(b * S_ + s)) * 256 + dim] = make_float2(d.z, d.w);
    }
}

// ======================================================================
// Kernel 3: out_proj GEMM (tf32 MMA) + fused max-pool (R7 body).
// Grid (2, 128): x = n-block, y = m-block (L2 reuse of A tile).
// ======================================================================
__global__ void __launch_bounds__(256) proj_pool_gemm(const float* __restrict__ W,
                                                      const float* __restrict__ bias) {
    __shared__ unsigned As[128 * ASTR];
    __shared__ unsigned Ws[128 * ASTR];

    const int tid = threadIdx.x;
    const int wid = tid >> 5, lane = tid & 31;
    const int wm = wid & 3, wn = wid >> 2;
    const int qr = lane >> 2, qc = lane & 3;
    const int m0 = blockIdx.y * 128, n0 = blockIdx.x * 128;

    float4 c[2][8] = {};

    for (int kt = 0; kt < 256; kt += 32) {
        __syncthreads();
        #pragma unroll
        for (int it = 0; it < 4; ++it) {
            int idx = tid + it * 256;
            int row = idx >> 3;
            int c4  = (idx & 7) * 4;
            float4 av = *(const float4*)&g_attn[(size_t)(m0 + row) * 256 + kt + c4];
            unsigned u0,u1,u2,u3;
            TF32(u0, av.x); TF32(u1, av.y); TF32(u2, av.z); TF32(u3, av.w);
            *(uint4*)&As[row * ASTR + c4] = make_uint4(u0,u1,u2,u3);
            float4 wv = *(const float4*)&W[(size_t)(n0 + row) * 256 + kt + c4];
            TF32(u0, wv.x); TF32(u1, wv.y); TF32(u2, wv.z); TF32(u3, wv.w);
            *(uint4*)&Ws[row * ASTR + c4] = make_uint4(u0,u1,u2,u3);
        }
        __syncthreads();
        #pragma unroll
        for (int ks = 0; ks < 4; ++ks) {
            const int k0 = ks * 8;
            unsigned a[2][4], b[8][2];
            #pragma unroll
            for (int mt = 0; mt < 2; ++mt) {
                int rb = wm * 32 + mt * 16 + qr;
                a[mt][0] = As[(rb    ) * ASTR + k0 + qc];
                a[mt][1] = As[(rb + 8) * ASTR + k0 + qc];
                a[mt][2] = As[(rb    ) * ASTR + k0 + qc + 4];
                a[mt][3] = As[(rb + 8) * ASTR + k0 + qc + 4];
            }
            #pragma unroll
            for (int nt = 0; nt < 8; ++nt) {
                int nb = wn * 64 + nt * 8 + qr;
                b[nt][0] = Ws[nb * ASTR + k0 + qc];
                b[nt][1] = Ws[nb * ASTR + k0 + qc + 4];
            }
            #pragma unroll
            for (int mt = 0; mt < 2; ++mt)
                #pragma unroll
                for (int nt = 0; nt < 8; ++nt)
                    MMA_TF32(c[mt][nt], a[mt], b[nt]);
        }
    }

    float v0[8], v1[8];
    #pragma unroll
    for (int nt = 0; nt < 8; ++nt) {
        v0[nt] = fmaxf(fmaxf(c[0][nt].x, c[0][nt].z), fmaxf(c[1][nt].x, c[1][nt].z));
        v1[nt] = fmaxf(fmaxf(c[0][nt].y, c[0][nt].w), fmaxf(c[1][nt].y, c[1][nt].w));
    }
    #pragma unroll
    for (int off = 4; off <= 16; off <<= 1) {
        #pragma unroll
        for (int nt = 0; nt < 8; ++nt) {
            v0[nt] = fmaxf(v0[nt], __shfl_xor_sync(0xffffffffu, v0[nt], off));
            v1[nt] = fmaxf(v1[nt], __shfl_xor_sync(0xffffffffu, v1[nt], off));
        }
    }
    if (lane < 4) {
        const int bb = m0 >> 11;
        #pragma unroll
        for (int nt = 0; nt < 8; ++nt) {
            int n_g = n0 + wn * 64 + nt * 8 + 2 * lane;
            atomicMax(&g_ctx_u[bb * 256 + n_g],     f2ord(v0[nt] + bias[n_g]));
            atomicMax(&g_ctx_u[bb * 256 + n_g + 1], f2ord(v1[nt] + bias[n_g + 1]));
        }
    }
}

// ======================================================================
// MLP head.
// ======================================================================
__global__ void __launch_bounds__(256) fc1_kernel(const float* __restrict__ w,
                                                  const float* __restrict__ bias) {
    const int gid = blockIdx.x * 8 + (threadIdx.x >> 5);
    const int lane = threadIdx.x & 31;
    const int b = gid >> 9, o = gid & 511;
    const float* wr = w + (size_t)o * 256 + lane * 8;
    const unsigned* xr = g_ctx_u + b * 256 + lane * 8;
    float4 w0 = *(const float4*)wr,  w1 = *(const float4*)(wr + 4);
    uint4 xu0 = *(const uint4*)xr,   xu1 = *(const uint4*)(xr + 4);
    float acc = w0.x*ord2f(xu0.x) + w0.y*ord2f(xu0.y) + w0.z*ord2f(xu0.z) + w0.w*ord2f(xu0.w)
              + w1.x*ord2f(xu1.x) + w1.y*ord2f(xu1.y) + w1.z*ord2f(xu1.z) + w1.w*ord2f(xu1.w);
    #pragma unroll
    for (int off = 16; off > 0; off >>= 1)
        acc += __shfl_xor_sync(0xffffffffu, acc, off);
    if (lane == 0) {
        acc += bias[o];
        g_h1[gid] = acc > 0.f ? acc : 0.01f * acc;
    }
}

__global__ void __launch_bounds__(256) fc2_kernel(const float* __restrict__ w,
                                                  const float* __restrict__ bias) {
    const int gid = blockIdx.x * 8 + (threadIdx.x >> 5);
    const int lane = threadIdx.x & 31;
    const int b = gid >> 8, o = gid & 255;
    const float* wr = w + (size_t)o * 512 + lane * 16;
    const float* xr = g_h1 + b * 512 + lane * 16;
    float acc = 0.f;
    #pragma unroll
    for (int cc = 0; cc < 4; ++cc) {
        float4 wv = *(const float4*)(wr + cc * 4);
        float4 xv = *(const float4*)(xr + cc * 4);
        acc += wv.x*xv.x + wv.y*xv.y + wv.z*xv.z + wv.w*xv.w;
    }
    #pragma unroll
    for (int off = 16; off > 0; off >>= 1)
        acc += __shfl_xor_sync(0xffffffffu, acc, off);
    if (lane == 0) {
        acc += bias[o];
        g_h2[gid] = acc > 0.f ? acc : 0.01f * acc;
    }
}

__global__ void __launch_bounds__(256) fc3_kernel(const float* __restrict__ w,
                                                  const float* __restrict__ bias,
                                                  float* __restrict__ out) {
    const int gid = blockIdx.x * 8 + (threadIdx.x >> 5);
    const int lane = threadIdx.x & 31;
    if (gid >= 8 * 20) return;
    const int b = gid / 20, o = gid % 20;
    const float* wr = w + (size_t)o * 256 + lane * 8;
    const float* xr = g_h2 + b * 256 + lane * 8;
    float4 w0 = *(const float4*)wr,  w1 = *(const float4*)(wr + 4);
    float4 x0 = *(const float4*)xr,  x1 = *(const float4*)(xr + 4);
    float acc = w0.x*x0.x + w0.y*x0.y + w0.z*x0.z + w0.w*x0.w
              + w1.x*x1.x + w1.y*x1.y + w1.z*x1.z + w1.w*x1.w;
    #pragma unroll
    for (int off = 16; off > 0; off >>= 1)
        acc += __shfl_xor_sync(0xffffffffu, acc, off);
    if (lane == 0) out[b * 20 + o] = acc + bias[o];
}

// ======================================================================
extern "C" void kernel_launch(void* const* d_in, const int* in_sizes, int n_in,
                              void* d_out, int out_size) {
    const int*   text = (const int*)d_in[0];
    const float* emb  = (const float*)d_in[1];
    const float* ipw  = (const float*)d_in[2];
    const float* ipb  = (const float*)d_in[3];
    const float* opw  = (const float*)d_in[4];
    const float* opb  = (const float*)d_in[5];
    const float* fc1w = (const float*)d_in[6];
    const float* fc1b = (const float*)d_in[7];
    const float* fc2w = (const float*)d_in[8];
    const float* fc2b = (const float*)d_in[9];
    const float* fc3w = (const float*)d_in[10];
    const float* fc3b = (const float*)d_in[11];
    float* out = (float*)d_out;

    qkv_gemm<<<dim3(6, M_TOT / 128), 256>>>(text, emb, ipw, ipb);

    const int attn_smem = (WROWS * KSTR + QT * KSTR + 64 * VSTR
                           + QT * SSTR + QT * PSTR) * sizeof(float);
    cudaFuncSetAttribute(attn_kernel, cudaFuncAttributeMaxDynamicSharedMemorySize, attn_smem);
    attn_kernel<<<B_ * H_ * (S_ / QT), 256, attn_smem>>>();

    proj_pool_gemm<<<dim3(2, M_TOT / 128), 256>>>(opw, opb);

    fc1_kernel<<<512, 256>>>(fc1w, fc1b);
    fc2_kernel<<<256, 256>>>(fc2w, fc2b);
    fc3_kernel<<<20, 256>>>(fc3w, fc3b, out);
}

// round 12
// speedup vs baseline: 1.1751x; 1.1516x over previous
#include <cuda_runtime.h>
#include <cuda_bf16.h>

#define B_   8
#define S_   2048
#define E_   256
#define H_   4
#define D_   64
#define M_TOT (B_*S_)
#define QT   16
#define WROWS 144
#define KSTR 68
#define VSTR 145
#define SSTR 148
#define PSTR 148

typedef unsigned long long u64;

#define TF32(o, x) asm("cvt.rna.tf32.f32 %0, %1;" : "=r"(o) : "f"(x))
__device__ __forceinline__ float tf32r(float x) {
    unsigned u; TF32(u, x); return __uint_as_float(u);
}
#define MMA_TF32(c, a, b) \
    asm("mma.sync.aligned.m16n8k8.row.col.f32.tf32.tf32.f32 " \
        "{%0,%1,%2,%3}, {%4,%5,%6,%7}, {%8,%9}, {%0,%1,%2,%3};" \
        : "+f"((c).x), "+f"((c).y), "+f"((c).z), "+f"((c).w) \
        : "r"((a)[0]), "r"((a)[1]), "r"((a)[2]), "r"((a)[3]), \
          "r"((b)[0]), "r"((b)[1]))

#define ASTR 36   // GEMM smem stride (words): fragment bank = lane id

// -------- scratch --------
__device__ float g_x[(size_t)M_TOT * E_];           // rounded gathered embeddings
__device__ float g_wi[768 * 256];                   // rounded in_proj_w
__device__ float g_wo[256 * 256];                   // rounded out_proj_w
__device__ float g_qkv[3ull * B_ * H_ * S_ * D_];   // rounded q/k/v
__device__ float g_attn[(size_t)M_TOT * E_];        // rounded attn out
__device__ unsigned int g_ctx_u[B_ * E_];
__device__ float g_h1[B_ * 512];
__device__ float g_h2[B_ * 256];

__device__ __forceinline__ unsigned int f2ord(float f) {
    unsigned int u = __float_as_uint(f);
    return (u & 0x80000000u) ? ~u : (u | 0x80000000u);
}
__device__ __forceinline__ float ord2f(unsigned int u) {
    return (u & 0x80000000u) ? __uint_as_float(u & 0x7FFFFFFFu)
                             : __uint_as_float(~u);
}

__global__ void init_ctx() {
    g_ctx_u[blockIdx.x * 256 + threadIdx.x] = 0u;
}

// ======================================================================
// Kernel 0: producer-side rounding. Gathers X=rna(emb[text]) and rounds
// both weight matrices. float4 granularity.
// ======================================================================
#define NX  (M_TOT * 64)          // X float4 count (256 floats = 64 f4 / row)
#define NWI (768 * 64)
#define NWO (256 * 64)
__global__ void __launch_bounds__(256) prep_kernel(const int* __restrict__ text,
                                                   const float* __restrict__ emb,
                                                   const float* __restrict__ wi,
                                                   const float* __restrict__ wo) {
    const int total = NX + NWI + NWO;
    for (int i = blockIdx.x * 256 + threadIdx.x; i < total; i += gridDim.x * 256) {
        float4 v; float4* dst;
        if (i < NX) {
            int m = i >> 6, c4 = i & 63;
            v = ((const float4*)emb)[(size_t)text[m] * 64 + c4];
            dst = (float4*)g_x + i;
        } else if (i < NX + NWI) {
            int j = i - NX;
            v = ((const float4*)wi)[j];
            dst = (float4*)g_wi + j;
        } else {
            int j = i - NX - NWI;
            v = ((const float4*)wo)[j];
            dst = (float4*)g_wo + j;
        }
        v.x = tf32r(v.x); v.y = tf32r(v.y); v.z = tf32r(v.z); v.w = tf32r(v.w);
        *dst = v;
    }
}

// ======================================================================
// Kernel 1: QKV GEMM on pre-rounded X/W (no cvt anywhere). R7 structure.
// Epilogue rounds outputs (idempotent for attn staging).
// ======================================================================
__global__ void __launch_bounds__(256) qkv_gemm(const float* __restrict__ bias) {
    __shared__ unsigned As[128 * ASTR];
    __shared__ unsigned Ws[128 * ASTR];

    const int tid = threadIdx.x;
    const int wid = tid >> 5, lane = tid & 31;
    const int wm = wid & 3, wn = wid >> 2;
    const int qr = lane >> 2, qc = lane & 3;
    const int m0 = blockIdx.x * 128, n0 = blockIdx.y * 128;

    float4 c[2][8] = {};

    for (int kt = 0; kt < 256; kt += 32) {
        __syncthreads();
        #pragma unroll
        for (int it = 0; it < 4; ++it) {
            int idx = tid + it * 256;
            int row = idx >> 3;
            int c4  = (idx & 7) * 4;
            *(uint4*)&As[row * ASTR + c4] =
                *(const uint4*)&g_x[(size_t)(m0 + row) * 256 + kt + c4];
            *(uint4*)&Ws[row * ASTR + c4] =
                *(const uint4*)&g_wi[(size_t)(n0 + row) * 256 + kt + c4];
        }
        __syncthreads();
        #pragma unroll
        for (int ks = 0; ks < 4; ++ks) {
            const int k0 = ks * 8;
            unsigned a[2][4], b[8][2];
            #pragma unroll
            for (int mt = 0; mt < 2; ++mt) {
                int rb = wm * 32 + mt * 16 + qr;
                a[mt][0] = As[(rb    ) * ASTR + k0 + qc];
                a[mt][1] = As[(rb + 8) * ASTR + k0 + qc];
                a[mt][2] = As[(rb    ) * ASTR + k0 + qc + 4];
                a[mt][3] = As[(rb + 8) * ASTR + k0 + qc + 4];
            }
            #pragma unroll
            for (int nt = 0; nt < 8; ++nt) {
                int nb = wn * 64 + nt * 8 + qr;
                b[nt][0] = Ws[nb * ASTR + k0 + qc];
                b[nt][1] = Ws[nb * ASTR + k0 + qc + 4];
            }
            #pragma unroll
            for (int mt = 0; mt < 2; ++mt)
                #pragma unroll
                for (int nt = 0; nt < 8; ++nt)
                    MMA_TF32(c[mt][nt], a[mt], b[nt]);
        }
    }

    #pragma unroll
    for (int nt = 0; nt < 8; ++nt) {
        const int n_g = n0 + wn * 64 + nt * 8 + 2 * qc;
        const int sec = n_g >> 8;
        const int h   = (n_g >> 6) & 3;
        const int d   = n_g & 63;
        const float scale = (sec == 0) ? 0.125f : 1.0f;
        const float b0v = bias[n_g], b1v = bias[n_g + 1];
        #pragma unroll
        for (int mt = 0; mt < 2; ++mt) {
            float4 cc = c[mt][nt];
            int r = wm * 32 + mt * 16 + qr;
            #pragma unroll
            for (int half = 0; half < 2; ++half) {
                int m = m0 + r + half * 8;
                int bb = m >> 11, s = m & 2047;
                float2 o;
                o.x = tf32r(((half ? cc.z : cc.x) + b0v) * scale);
                o.y = tf32r(((half ? cc.w : cc.y) + b1v) * scale);
                *(float2*)&g_qkv[((((size_t)sec * B_ + bb) * H_ + h) * S_ + s) * 64 + d] = o;
            }
        }
    }
}

// ======================================================================
// Kernel 2: banded attention (R7 structure, staging without cvt;
// epilogue rounds D).
// ======================================================================
__global__ void __launch_bounds__(256) attn_kernel() {
    extern __shared__ float smem[];
    float* K_s = smem;
    float* Q_s = K_s + WROWS * KSTR;
    float* V_s = Q_s + QT * KSTR;
    float* S_s = V_s + 64 * VSTR;
    float* P_s = S_s + QT * SSTR;
    unsigned* Ku = (unsigned*)K_s;
    unsigned* Qu = (unsigned*)Q_s;
    unsigned* Vu = (unsigned*)V_s;
    unsigned* Pu = (unsigned*)P_s;

    const int nq = S_ / QT;
    const int qt = blockIdx.x % nq;
    const int h  = (blockIdx.x / nq) % H_;
    const int b  = blockIdx.x / (nq * H_);

    const int q0 = qt * QT;
    const int kstart = q0 - 64;

    const float* qb = g_qkv + ((size_t)(b * H_ + h)) * S_ * 64;
    const float* kb = g_qkv + ((size_t)(B_ * H_) + b * H_ + h) * S_ * 64;
    const float* vb = g_qkv + ((size_t)(2 * B_ * H_) + b * H_ + h) * S_ * 64;

    const int tid = threadIdx.x;
    const int wid = tid >> 5, lane = tid & 31;
    const int qr = lane >> 2, qc = lane & 3;

    for (int idx = tid; idx < WROWS * 16; idx += 256) {
        int row = idx >> 4, d4 = (idx & 15) * 4;
        int kg = kstart + row;
        bool in = (kg >= 0) && (kg < S_);
        float4 kv = in ? *(const float4*)&kb[(size_t)kg * 64 + d4]
                       : make_float4(0.f,0.f,0.f,0.f);
        *(float4*)&K_s[row * KSTR + d4] = kv;
        float4 vv = in ? *(const float4*)&vb[(size_t)kg * 64 + d4]
                       : make_float4(0.f,0.f,0.f,0.f);
        V_s[(d4+0) * VSTR + row] = vv.x;
        V_s[(d4+1) * VSTR + row] = vv.y;
        V_s[(d4+2) * VSTR + row] = vv.z;
        V_s[(d4+3) * VSTR + row] = vv.w;
    }
    if (tid < QT * 16) {
        int r = tid >> 4, d4 = (tid & 15) * 4;
        *(float4*)&Q_s[r * KSTR + d4] = *(const float4*)&qb[(size_t)(q0 + r) * 64 + d4];
    }
    __syncthreads();

    for (int tt = wid; tt < 18; tt += 8) {
        float4 c = {0.f, 0.f, 0.f, 0.f};
        #pragma unroll
        for (int ks = 0; ks < 8; ++ks) {
            const int k0 = ks * 8;
            unsigned a[4], bf[2];
            a[0] = Qu[qr * KSTR + k0 + qc];
            a[1] = Qu[(qr + 8) * KSTR + k0 + qc];
            a[2] = Qu[qr * KSTR + k0 + qc + 4];
            a[3] = Qu[(qr + 8) * KSTR + k0 + qc + 4];
            bf[0] = Ku[(tt * 8 + qr) * KSTR + k0 + qc];
            bf[1] = Ku[(tt * 8 + qr) * KSTR + k0 + qc + 4];
            MMA_TF32(c, a, bf);
        }
        *(float2*)&S_s[qr * SSTR + tt * 8 + 2 * qc]       = make_float2(c.x, c.y);
        *(float2*)&S_s[(qr + 8) * SSTR + tt * 8 + 2 * qc] = make_float2(c.z, c.w);
    }
    __syncthreads();

    #pragma unroll
    for (int rr = 0; rr < 2; ++rr) {
        const int row = wid * 2 + rr;
        float sc[5];
        #pragma unroll
        for (int r = 0; r < 5; ++r) {
            int t = lane + 32 * r;
            int j = row + t;
            int kg = kstart + j;
            bool valid = (t <= 128) && (kg >= 0) && (kg < S_);
            sc[r] = valid ? S_s[row * SSTR + j] : -3.0e38f;
        }
        float mx = sc[0];
        #pragma unroll
        for (int r = 1; r < 5; ++r) mx = fmaxf(mx, sc[r]);
        #pragma unroll
        for (int off = 16; off > 0; off >>= 1)
            mx = fmaxf(mx, __shfl_xor_sync(0xffffffffu, mx, off));
        float sum = 0.f;
        #pragma unroll
        for (int r = 0; r < 5; ++r) { sc[r] = __expf(sc[r] - mx); sum += sc[r]; }
        #pragma unroll
        for (int off = 16; off > 0; off >>= 1)
            sum += __shfl_xor_sync(0xffffffffu, sum, off);
        float inv = 1.0f / sum;

        #pragma unroll
        for (int t = lane; t < WROWS; t += 32) Pu[row * PSTR + t] = 0u;
        __syncwarp();
        #pragma unroll
        for (int r = 0; r < 5; ++r) {
            int t = lane + 32 * r;
            if (t <= 128) {
                float p = sc[r] * inv;
                unsigned u; TF32(u, p);
                Pu[row * PSTR + row + t] = u;
            }
        }
        __syncwarp();
    }
    __syncthreads();

    float4 d = {0.f, 0.f, 0.f, 0.f};
    #pragma unroll
    for (int ks = 0; ks < 18; ++ks) {
        const int k0 = ks * 8;
        unsigned a[4], bf[2];
        a[0] = Pu[qr * PSTR + k0 + qc];
        a[1] = Pu[(qr + 8) * PSTR + k0 + qc];
        a[2] = Pu[qr * PSTR + k0 + qc + 4];
        a[3] = Pu[(qr + 8) * PSTR + k0 + qc + 4];
        bf[0] = Vu[(wid * 8 + qr) * VSTR + k0 + qc];
        bf[1] = Vu[(wid * 8 + qr) * VSTR + k0 + qc + 4];
        MMA_TF32(d, a, bf);
    }
    const int dim = h * 64 + wid * 8 + 2 * qc;
    {
        int s = q0 + qr;
        *(float2*)&g_attn[((size_t)(b * S_ + s)) * 256 + dim] =
            make_float2(tf32r(d.x), tf32r(d.y));
        s = q0 + qr + 8;
        *(float2*)&g_attn[((size_t)(b * S_ + s)) * 256 + dim] =
            make_float2(tf32r(d.z), tf32r(d.w));
    }
}

// ======================================================================
// Kernel 3: out_proj GEMM on pre-rounded inputs + fused max-pool.
// ======================================================================
__global__ void __launch_bounds__(256) proj_pool_gemm(const float* __restrict__ bias) {
    __shared__ unsigned As[128 * ASTR];
    __shared__ unsigned Ws[128 * ASTR];

    const int tid = threadIdx.x;
    const int wid = tid >> 5, lane = tid & 31;
    const int wm = wid & 3, wn = wid >> 2;
    const int qr = lane >> 2, qc = lane & 3;
    const int m0 = blockIdx.x * 128, n0 = blockIdx.y * 128;

    float4 c[2][8] = {};

    for (int kt = 0; kt < 256; kt += 32) {
        __syncthreads();
        #pragma unroll
        for (int it = 0; it < 4; ++it) {
            int idx = tid + it * 256;
            int row = idx >> 3;
            int c4  = (idx & 7) * 4;
            *(uint4*)&As[row * ASTR + c4] =
                *(const uint4*)&g_attn[(size_t)(m0 + row) * 256 + kt + c4];
            *(uint4*)&Ws[row * ASTR + c4] =
                *(const uint4*)&g_wo[(size_t)(n0 + row) * 256 + kt + c4];
        }
        __syncthreads();
        #pragma unroll
        for (int ks = 0; ks < 4; ++ks) {
            const int k0 = ks * 8;
            unsigned a[2][4], b[8][2];
            #pragma unroll
            for (int mt = 0; mt < 2; ++mt) {
                int rb = wm * 32 + mt * 16 + qr;
                a[mt][0] = As[(rb    ) * ASTR + k0 + qc];
                a[mt][1] = As[(rb + 8) * ASTR + k0 + qc];
                a[mt][2] = As[(rb    ) * ASTR + k0 + qc + 4];
                a[mt][3] = As[(rb + 8) * ASTR + k0 + qc + 4];
            }
            #pragma unroll
            for (int nt = 0; nt < 8; ++nt) {
                int nb = wn * 64 + nt * 8 + qr;
                b[nt][0] = Ws[nb * ASTR + k0 + qc];
                b[nt][1] = Ws[nb * ASTR + k0 + qc + 4];
            }
            #pragma unroll
            for (int mt = 0; mt < 2; ++mt)
                #pragma unroll
                for (int nt = 0; nt < 8; ++nt)
                    MMA_TF32(c[mt][nt], a[mt], b[nt]);
        }
    }

    float v0[8], v1[8];
    #pragma unroll
    for (int nt = 0; nt < 8; ++nt) {
        v0[nt] = fmaxf(fmaxf(c[0][nt].x, c[0][nt].z), fmaxf(c[1][nt].x, c[1][nt].z));
        v1[nt] = fmaxf(fmaxf(c[0][nt].y, c[0][nt].w), fmaxf(c[1][nt].y, c[1][nt].w));
    }
    #pragma unroll
    for (int off = 4; off <= 16; off <<= 1) {
        #pragma unroll
        for (int nt = 0; nt < 8; ++nt) {
            v0[nt] = fmaxf(v0[nt], __shfl_xor_sync(0xffffffffu, v0[nt], off));
            v1[nt] = fmaxf(v1[nt], __shfl_xor_sync(0xffffffffu, v1[nt], off));
        }
    }
    if (lane < 4) {
        const int bb = m0 >> 11;
        #pragma unroll
        for (int nt = 0; nt < 8; ++nt) {
            int n_g = n0 + wn * 64 + nt * 8 + 2 * lane;
            atomicMax(&g_ctx_u[bb * 256 + n_g],     f2ord(v0[nt] + bias[n_g]));
            atomicMax(&g_ctx_u[bb * 256 + n_g + 1], f2ord(v1[nt] + bias[n_g + 1]));
        }
    }
}

// ======================================================================
// MLP head.
// ======================================================================
__global__ void __launch_bounds__(256) fc1_kernel(const float* __restrict__ w,
                                                  const float* __restrict__ bias) {
    const int gid = blockIdx.x * 8 + (threadIdx.x >> 5);
    const int lane = threadIdx.x & 31;
    const int b = gid >> 9, o = gid & 511;
    const float* wr = w + (size_t)o * 256 + lane * 8;
    const unsigned* xr = g_ctx_u + b * 256 + lane * 8;
    float4 w0 = *(const float4*)wr,  w1 = *(const float4*)(wr + 4);
    uint4 xu0 = *(const uint4*)xr,   xu1 = *(const uint4*)(xr + 4);
    float acc = w0.x*ord2f(xu0.x) + w0.y*ord2f(xu0.y) + w0.z*ord2f(xu0.z) + w0.w*ord2f(xu0.w)
              + w1.x*ord2f(xu1.x) + w1.y*ord2f(xu1.y) + w1.z*ord2f(xu1.z) + w1.w*ord2f(xu1.w);
    #pragma unroll
    for (int off = 16; off > 0; off >>= 1)
        acc += __shfl_xor_sync(0xffffffffu, acc, off);
    if (lane == 0) {
        acc += bias[o];
        g_h1[gid] = acc > 0.f ? acc : 0.01f * acc;
    }
}

__global__ void __launch_bounds__(256) fc2_kernel(const float* __restrict__ w,
                                                  const float* __restrict__ bias) {
    const int gid = blockIdx.x * 8 + (threadIdx.x >> 5);
    const int lane = threadIdx.x & 31;
    const int b = gid >> 8, o = gid & 255;
    const float* wr = w + (size_t)o * 512 + lane * 16;
    const float* xr = g_h1 + b * 512 + lane * 16;
    float acc = 0.f;
    #pragma unroll
    for (int cc = 0; cc < 4; ++cc) {
        float4 wv = *(const float4*)(wr + cc * 4);
        float4 xv = *(const float4*)(xr + cc * 4);
        acc += wv.x*xv.x + wv.y*xv.y + wv.z*xv.z + wv.w*xv.w;
    }
    #pragma unroll
    for (int off = 16; off > 0; off >>= 1)
        acc += __shfl_xor_sync(0xffffffffu, acc, off);
    if (lane == 0) {
        acc += bias[o];
        g_h2[gid] = acc > 0.f ? acc : 0.01f * acc;
    }
}

__global__ void __launch_bounds__(256) fc3_kernel(const float* __restrict__ w,
                                                  const float* __restrict__ bias,
                                                  float* __restrict__ out) {
    const int gid = blockIdx.x * 8 + (threadIdx.x >> 5);
    const int lane = threadIdx.x & 31;
    if (gid >= 8 * 20) return;
    const int b = gid / 20, o = gid % 20;
    const float* wr = w + (size_t)o * 256 + lane * 8;
    const float* xr = g_h2 + b * 256 + lane * 8;
    float4 w0 = *(const float4*)wr,  w1 = *(const float4*)(wr + 4);
    float4 x0 = *(const float4*)xr,  x1 = *(const float4*)(xr + 4);
    float acc = w0.x*x0.x + w0.y*x0.y + w0.z*x0.z + w0.w*x0.w
              + w1.x*x1.x + w1.y*x1.y + w1.z*x1.z + w1.w*x1.w;
    #pragma unroll
    for (int off = 16; off > 0; off >>= 1)
        acc += __shfl_xor_sync(0xffffffffu, acc, off);
    if (lane == 0) out[b * 20 + o] = acc + bias[o];
}

// ======================================================================
extern "C" void kernel_launch(void* const* d_in, const int* in_sizes, int n_in,
                              void* d_out, int out_size) {
    const int*   text = (const int*)d_in[0];
    const float* emb  = (const float*)d_in[1];
    const float* ipw  = (const float*)d_in[2];
    const float* ipb  = (const float*)d_in[3];
    const float* opw  = (const float*)d_in[4];
    const float* opb  = (const float*)d_in[5];
    const float* fc1w = (const float*)d_in[6];
    const float* fc1b = (const float*)d_in[7];
    const float* fc2w = (const float*)d_in[8];
    const float* fc2b = (const float*)d_in[9];
    const float* fc3w = (const float*)d_in[10];
    const float* fc3b = (const float*)d_in[11];
    float* out = (float*)d_out;

    prep_kernel<<<448, 256>>>(text, emb, ipw, opw);
    init_ctx<<<8, 256>>>();

    qkv_gemm<<<dim3(M_TOT / 128, 6), 256>>>(ipb);

    const int attn_smem = (WROWS * KSTR + QT * KSTR + 64 * VSTR
                           + QT * SSTR + QT * PSTR) * sizeof(float);
    cudaFuncSetAttribute(attn_kernel, cudaFuncAttributeMaxDynamicSharedMemorySize, attn_smem);
    attn_kernel<<<B_ * H_ * (S_ / QT), 256, attn_smem>>>();

    proj_pool_gemm<<<dim3(M_TOT / 128, 2), 256>>>(opb);

    fc1_kernel<<<512, 256>>>(fc1w, fc1b);
    fc2_kernel<<<256, 256>>>(fc2w, fc2b);
    fc3_kernel<<<20, 256>>>(fc3w, fc3b, out);
}

// round 13
// speedup vs baseline: 1.2008x; 1.0219x over previous
#include <cuda_runtime.h>
#include <cuda_bf16.h>

#define B_   8
#define S_   2048
#define E_   256
#define H_   4
#define D_   64
#define M_TOT (B_*S_)
#define QT   16
#define WROWS 144
#define KSTR 68
#define VSTR 145
#define SSTR 148
#define PSTR 148
#define AT_THR 512

typedef unsigned long long u64;

#define TF32(o, x) asm("cvt.rna.tf32.f32 %0, %1;" : "=r"(o) : "f"(x))
__device__ __forceinline__ float tf32r(float x) {
    unsigned u; TF32(u, x); return __uint_as_float(u);
}
#define MMA_TF32(c, a, b) \
    asm("mma.sync.aligned.m16n8k8.row.col.f32.tf32.tf32.f32 " \
        "{%0,%1,%2,%3}, {%4,%5,%6,%7}, {%8,%9}, {%0,%1,%2,%3};" \
        : "+f"((c).x), "+f"((c).y), "+f"((c).z), "+f"((c).w) \
        : "r"((a)[0]), "r"((a)[1]), "r"((a)[2]), "r"((a)[3]), \
          "r"((b)[0]), "r"((b)[1]))

#define ASTR 36   // GEMM smem stride (words): fragment bank = lane id

// -------- scratch --------
__device__ float g_x[(size_t)M_TOT * E_];           // rounded gathered embeddings
__device__ float g_wi[768 * 256];                   // rounded in_proj_w
__device__ float g_wo[256 * 256];                   // rounded out_proj_w
__device__ float g_qkv[3ull * B_ * H_ * S_ * D_];   // rounded q/k/v
__device__ float g_attn[(size_t)M_TOT * E_];        // rounded attn out
__device__ unsigned int g_ctx_u[B_ * E_];
__device__ float g_h1[B_ * 512];
__device__ float g_h2[B_ * 256];

__device__ __forceinline__ unsigned int f2ord(float f) {
    unsigned int u = __float_as_uint(f);
    return (u & 0x80000000u) ? ~u : (u | 0x80000000u);
}
__device__ __forceinline__ float ord2f(unsigned int u) {
    return (u & 0x80000000u) ? __uint_as_float(u & 0x7FFFFFFFu)
                             : __uint_as_float(~u);
}

// ======================================================================
// Kernel 0: producer-side rounding + ctx init.
// ======================================================================
#define NX  (M_TOT * 64)
#define NWI (768 * 64)
#define NWO (256 * 64)
__global__ void __launch_bounds__(256) prep_kernel(const int* __restrict__ text,
                                                   const float* __restrict__ emb,
                                                   const float* __restrict__ wi,
                                                   const float* __restrict__ wo) {
    if (blockIdx.x < 8) g_ctx_u[blockIdx.x * 256 + threadIdx.x] = 0u;
    const int total = NX + NWI + NWO;
    for (int i = blockIdx.x * 256 + threadIdx.x; i < total; i += gridDim.x * 256) {
        float4 v; float4* dst;
        if (i < NX) {
            int m = i >> 6, c4 = i & 63;
            v = ((const float4*)emb)[(size_t)text[m] * 64 + c4];
            dst = (float4*)g_x + i;
        } else if (i < NX + NWI) {
            int j = i - NX;
            v = ((const float4*)wi)[j];
            dst = (float4*)g_wi + j;
        } else {
            int j = i - NX - NWI;
            v = ((const float4*)wo)[j];
            dst = (float4*)g_wo + j;
        }
        v.x = tf32r(v.x); v.y = tf32r(v.y); v.z = tf32r(v.z); v.w = tf32r(v.w);
        *dst = v;
    }
}

// ======================================================================
// Kernel 1: QKV GEMM on pre-rounded X/W (R12, unchanged).
// ======================================================================
__global__ void __launch_bounds__(256) qkv_gemm(const float* __restrict__ bias) {
    __shared__ unsigned As[128 * ASTR];
    __shared__ unsigned Ws[128 * ASTR];

    const int tid = threadIdx.x;
    const int wid = tid >> 5, lane = tid & 31;
    const int wm = wid & 3, wn = wid >> 2;
    const int qr = lane >> 2, qc = lane & 3;
    const int m0 = blockIdx.x * 128, n0 = blockIdx.y * 128;

    float4 c[2][8] = {};

    for (int kt = 0; kt < 256; kt += 32) {
        __syncthreads();
        #pragma unroll
        for (int it = 0; it < 4; ++it) {
            int idx = tid + it * 256;
            int row = idx >> 3;
            int c4  = (idx & 7) * 4;
            *(uint4*)&As[row * ASTR + c4] =
                *(const uint4*)&g_x[(size_t)(m0 + row) * 256 + kt + c4];
            *(uint4*)&Ws[row * ASTR + c4] =
                *(const uint4*)&g_wi[(size_t)(n0 + row) * 256 + kt + c4];
        }
        __syncthreads();
        #pragma unroll
        for (int ks = 0; ks < 4; ++ks) {
            const int k0 = ks * 8;
            unsigned a[2][4], b[8][2];
            #pragma unroll
            for (int mt = 0; mt < 2; ++mt) {
                int rb = wm * 32 + mt * 16 + qr;
                a[mt][0] = As[(rb    ) * ASTR + k0 + qc];
                a[mt][1] = As[(rb + 8) * ASTR + k0 + qc];
                a[mt][2] = As[(rb    ) * ASTR + k0 + qc + 4];
                a[mt][3] = As[(rb + 8) * ASTR + k0 + qc + 4];
            }
            #pragma unroll
            for (int nt = 0; nt < 8; ++nt) {
                int nb = wn * 64 + nt * 8 + qr;
                b[nt][0] = Ws[nb * ASTR + k0 + qc];
                b[nt][1] = Ws[nb * ASTR + k0 + qc + 4];
            }
            #pragma unroll
            for (int mt = 0; mt < 2; ++mt)
                #pragma unroll
                for (int nt = 0; nt < 8; ++nt)
                    MMA_TF32(c[mt][nt], a[mt], b[nt]);
        }
    }

    #pragma unroll
    for (int nt = 0; nt < 8; ++nt) {
        const int n_g = n0 + wn * 64 + nt * 8 + 2 * qc;
        const int sec = n_g >> 8;
        const int h   = (n_g >> 6) & 3;
        const int d   = n_g & 63;
        const float scale = (sec == 0) ? 0.125f : 1.0f;
        const float b0v = bias[n_g], b1v = bias[n_g + 1];
        #pragma unroll
        for (int mt = 0; mt < 2; ++mt) {
            float4 cc = c[mt][nt];
            int r = wm * 32 + mt * 16 + qr;
            #pragma unroll
            for (int half = 0; half < 2; ++half) {
                int m = m0 + r + half * 8;
                int bb = m >> 11, s = m & 2047;
                float2 o;
                o.x = tf32r(((half ? cc.z : cc.x) + b0v) * scale);
                o.y = tf32r(((half ? cc.w : cc.y) + b1v) * scale);
                *(float2*)&g_qkv[((((size_t)sec * B_ + bb) * H_ + h) * S_ + s) * 64 + d] = o;
            }
        }
    }
}

// ======================================================================
// Kernel 2: banded attention, 512 threads (16 warps), same smem layout.
// AV phase k-split across warp pairs, combined via K_s scratch.
// ======================================================================
__global__ void __launch_bounds__(AT_THR) attn_kernel() {
    extern __shared__ float smem[];
    float* K_s = smem;                     // [144][68]  (scratch in AV combine)
    float* Q_s = K_s + WROWS * KSTR;       // [16][68]
    float* V_s = Q_s + QT * KSTR;          // [64][145]
    float* S_s = V_s + 64 * VSTR;          // [16][148]
    float* P_s = S_s + QT * SSTR;          // [16][148]
    unsigned* Ku = (unsigned*)K_s;
    unsigned* Qu = (unsigned*)Q_s;
    unsigned* Vu = (unsigned*)V_s;
    unsigned* Pu = (unsigned*)P_s;

    const int nq = S_ / QT;
    const int qt = blockIdx.x % nq;
    const int h  = (blockIdx.x / nq) % H_;
    const int b  = blockIdx.x / (nq * H_);

    const int q0 = qt * QT;
    const int kstart = q0 - 64;

    const float* qb = g_qkv + ((size_t)(b * H_ + h)) * S_ * 64;
    const float* kb = g_qkv + ((size_t)(B_ * H_) + b * H_ + h) * S_ * 64;
    const float* vb = g_qkv + ((size_t)(2 * B_ * H_) + b * H_ + h) * S_ * 64;

    const int tid = threadIdx.x;
    const int wid = tid >> 5, lane = tid & 31;
    const int qr = lane >> 2, qc = lane & 3;

    // ---- stage K and V^T (pre-rounded bits; no cvt) ----
    for (int idx = tid; idx < WROWS * 16; idx += AT_THR) {
        int row = idx >> 4, d4 = (idx & 15) * 4;
        int kg = kstart + row;
        bool in = (kg >= 0) && (kg < S_);
        float4 kv = in ? *(const float4*)&kb[(size_t)kg * 64 + d4]
                       : make_float4(0.f,0.f,0.f,0.f);
        *(float4*)&K_s[row * KSTR + d4] = kv;
        float4 vv = in ? *(const float4*)&vb[(size_t)kg * 64 + d4]
                       : make_float4(0.f,0.f,0.f,0.f);
        V_s[(d4+0) * VSTR + row] = vv.x;
        V_s[(d4+1) * VSTR + row] = vv.y;
        V_s[(d4+2) * VSTR + row] = vv.z;
        V_s[(d4+3) * VSTR + row] = vv.w;
    }
    if (tid < QT * 16) {
        int r = tid >> 4, d4 = (tid & 15) * 4;
        *(float4*)&Q_s[r * KSTR + d4] = *(const float4*)&qb[(size_t)(q0 + r) * 64 + d4];
    }
    __syncthreads();

    // ---- scores: 18 n-tiles over 16 warps ----
    for (int tt = wid; tt < 18; tt += 16) {
        float4 c = {0.f, 0.f, 0.f, 0.f};
        #pragma unroll
        for (int ks = 0; ks < 8; ++ks) {
            const int k0 = ks * 8;
            unsigned a[4], bf[2];
            a[0] = Qu[qr * KSTR + k0 + qc];
            a[1] = Qu[(qr + 8) * KSTR + k0 + qc];
            a[2] = Qu[qr * KSTR + k0 + qc + 4];
            a[3] = Qu[(qr + 8) * KSTR + k0 + qc + 4];
            bf[0] = Ku[(tt * 8 + qr) * KSTR + k0 + qc];
            bf[1] = Ku[(tt * 8 + qr) * KSTR + k0 + qc + 4];
            MMA_TF32(c, a, bf);
        }
        *(float2*)&S_s[qr * SSTR + tt * 8 + 2 * qc]       = make_float2(c.x, c.y);
        *(float2*)&S_s[(qr + 8) * SSTR + tt * 8 + 2 * qc] = make_float2(c.z, c.w);
    }
    __syncthreads();

    // ---- softmax: warp wid handles row wid ----
    {
        const int row = wid;
        float sc[5];
        #pragma unroll
        for (int r = 0; r < 5; ++r) {
            int t = lane + 32 * r;
            int j = row + t;
            int kg = kstart + j;
            bool valid = (t <= 128) && (kg >= 0) && (kg < S_);
            sc[r] = valid ? S_s[row * SSTR + j] : -3.0e38f;
        }
        float mx = sc[0];
        #pragma unroll
        for (int r = 1; r < 5; ++r) mx = fmaxf(mx, sc[r]);
        #pragma unroll
        for (int off = 16; off > 0; off >>= 1)
            mx = fmaxf(mx, __shfl_xor_sync(0xffffffffu, mx, off));
        float sum = 0.f;
        #pragma unroll
        for (int r = 0; r < 5; ++r) { sc[r] = __expf(sc[r] - mx); sum += sc[r]; }
        #pragma unroll
        for (int off = 16; off > 0; off >>= 1)
            sum += __shfl_xor_sync(0xffffffffu, sum, off);
        float inv = 1.0f / sum;

        #pragma unroll
        for (int t = lane; t < WROWS; t += 32) Pu[row * PSTR + t] = 0u;
        __syncwarp();
        #pragma unroll
        for (int r = 0; r < 5; ++r) {
            int t = lane + 32 * r;
            if (t <= 128) {
                float p = sc[r] * inv;
                unsigned u; TF32(u, p);
                Pu[row * PSTR + row + t] = u;
            }
        }
    }
    __syncthreads();

    // ---- AV: 8 n-tiles x 2 k-halves over 16 warps; combine via K_s scratch ----
    {
        const int nt = wid & 7, half = wid >> 3;
        const int ks0 = half * 9;
        float4 d = {0.f, 0.f, 0.f, 0.f};
        #pragma unroll
        for (int ks = 0; ks < 9; ++ks) {
            const int k0 = (ks0 + ks) * 8;
            unsigned a[4], bf[2];
            a[0] = Pu[qr * PSTR + k0 + qc];
            a[1] = Pu[(qr + 8) * PSTR + k0 + qc];
            a[2] = Pu[qr * PSTR + k0 + qc + 4];
            a[3] = Pu[(qr + 8) * PSTR + k0 + qc + 4];
            bf[0] = Vu[(nt * 8 + qr) * VSTR + k0 + qc];
            bf[1] = Vu[(nt * 8 + qr) * VSTR + k0 + qc + 4];
            MMA_TF32(d, a, bf);
        }
        float* scr = K_s;   // K region is dead after the score phase
        if (half == 1)
            *(float4*)&scr[(nt * 32 + lane) * 4] = d;
        __syncthreads();
        if (half == 0) {
            float4 e = *(const float4*)&scr[(nt * 32 + lane) * 4];
            d.x += e.x; d.y += e.y; d.z += e.z; d.w += e.w;
            const int dim = h * 64 + nt * 8 + 2 * qc;
            int s = q0 + qr;
            *(float2*)&g_attn[((size_t)(b * S_ + s)) * 256 + dim] =
                make_float2(tf32r(d.x), tf32r(d.y));
            s = q0 + qr + 8;
            *(float2*)&g_attn[((size_t)(b * S_ + s)) * 256 + dim] =
                make_float2(tf32r(d.z), tf32r(d.w));
        }
    }
}

// ======================================================================
// Kernel 3: out_proj GEMM on pre-rounded inputs + fused max-pool (R12).
// ======================================================================
__global__ void __launch_bounds__(256) proj_pool_gemm(const float* __restrict__ bias) {
    __shared__ unsigned As[128 * ASTR];
    __shared__ unsigned Ws[128 * ASTR];

    const int tid = threadIdx.x;
    const int wid = tid >> 5, lane = tid & 31;
    const int wm = wid & 3, wn = wid >> 2;
    const int qr = lane >> 2, qc = lane & 3;
    const int m0 = blockIdx.x * 128, n0 = blockIdx.y * 128;

    float4 c[2][8] = {};

    for (int kt = 0; kt < 256; kt += 32) {
        __syncthreads();
        #pragma unroll
        for (int it = 0; it < 4; ++it) {
            int idx = tid + it * 256;
            int row = idx >> 3;
            int c4  = (idx & 7) * 4;
            *(uint4*)&As[row * ASTR + c4] =
                *(const uint4*)&g_attn[(size_t)(m0 + row) * 256 + kt + c4];
            *(uint4*)&Ws[row * ASTR + c4] =
                *(const uint4*)&g_wo[(size_t)(n0 + row) * 256 + kt + c4];
        }
        __syncthreads();
        #pragma unroll
        for (int ks = 0; ks < 4; ++ks) {
            const int k0 = ks * 8;
            unsigned a[2][4], b[8][2];
            #pragma unroll
            for (int mt = 0; mt < 2; ++mt) {
                int rb = wm * 32 + mt * 16 + qr;
                a[mt][0] = As[(rb    ) * ASTR + k0 + qc];
                a[mt][1] = As[(rb + 8) * ASTR + k0 + qc];
                a[mt][2] = As[(rb    ) * ASTR + k0 + qc + 4];
                a[mt][3] = As[(rb + 8) * ASTR + k0 + qc + 4];
            }
            #pragma unroll
            for (int nt = 0; nt < 8; ++nt) {
                int nb = wn * 64 + nt * 8 + qr;
                b[nt][0] = Ws[nb * ASTR + k0 + qc];
                b[nt][1] = Ws[nb * ASTR + k0 + qc + 4];
            }
            #pragma unroll
            for (int mt = 0; mt < 2; ++mt)
                #pragma unroll
                for (int nt = 0; nt < 8; ++nt)
                    MMA_TF32(c[mt][nt], a[mt], b[nt]);
        }
    }

    float v0[8], v1[8];
    #pragma unroll
    for (int nt = 0; nt < 8; ++nt) {
        v0[nt] = fmaxf(fmaxf(c[0][nt].x, c[0][nt].z), fmaxf(c[1][nt].x, c[1][nt].z));
        v1[nt] = fmaxf(fmaxf(c[0][nt].y, c[0][nt].w), fmaxf(c[1][nt].y, c[1][nt].w));
    }
    #pragma unroll
    for (int off = 4; off <= 16; off <<= 1) {
        #pragma unroll
        for (int nt = 0; nt < 8; ++nt) {
            v0[nt] = fmaxf(v0[nt], __shfl_xor_sync(0xffffffffu, v0[nt], off));
            v1[nt] = fmaxf(v1[nt], __shfl_xor_sync(0xffffffffu, v1[nt], off));
        }
    }
    if (lane < 4) {
        const int bb = m0 >> 11;
        #pragma unroll
        for (int nt = 0; nt < 8; ++nt) {
            int n_g = n0 + wn * 64 + nt * 8 + 2 * lane;
            atomicMax(&g_ctx_u[bb * 256 + n_g],     f2ord(v0[nt] + bias[n_g]));
            atomicMax(&g_ctx_u[bb * 256 + n_g + 1], f2ord(v1[nt] + bias[n_g + 1]));
        }
    }
}

// ======================================================================
// MLP head.
// ======================================================================
__global__ void __launch_bounds__(256) fc1_kernel(const float* __restrict__ w,
                                                  const float* __restrict__ bias) {
    const int gid = blockIdx.x * 8 + (threadIdx.x >> 5);
    const int lane = threadIdx.x & 31;
    const int b = gid >> 9, o = gid & 511;
    const float* wr = w + (size_t)o * 256 + lane * 8;
    const unsigned* xr = g_ctx_u + b * 256 + lane * 8;
    float4 w0 = *(const float4*)wr,  w1 = *(const float4*)(wr + 4);
    uint4 xu0 = *(const uint4*)xr,   xu1 = *(const uint4*)(xr + 4);
    float acc = w0.x*ord2f(xu0.x) + w0.y*ord2f(xu0.y) + w0.z*ord2f(xu0.z) + w0.w*ord2f(xu0.w)
              + w1.x*ord2f(xu1.x) + w1.y*ord2f(xu1.y) + w1.z*ord2f(xu1.z) + w1.w*ord2f(xu1.w);
    #pragma unroll
    for (int off = 16; off > 0; off >>= 1)
        acc += __shfl_xor_sync(0xffffffffu, acc, off);
    if (lane == 0) {
        acc += bias[o];
        g_h1[gid] = acc > 0.f ? acc : 0.01f * acc;
    }
}

__global__ void __launch_bounds__(256) fc2_kernel(const float* __restrict__ w,
                                                  const float* __restrict__ bias) {
    const int gid = blockIdx.x * 8 + (threadIdx.x >> 5);
    const int lane = threadIdx.x & 31;
    const int b = gid >> 8, o = gid & 255;
    const float* wr = w + (size_t)o * 512 + lane * 16;
    const float* xr = g_h1 + b * 512 + lane * 16;
    float acc = 0.f;
    #pragma unroll
    for (int cc = 0; cc < 4; ++cc) {
        float4 wv = *(const float4*)(wr + cc * 4);
        float4 xv = *(const float4*)(xr + cc * 4);
        acc += wv.x*xv.x + wv.y*xv.y + wv.z*xv.z + wv.w*xv.w;
    }
    #pragma unroll
    for (int off = 16; off > 0; off >>= 1)
        acc += __shfl_xor_sync(0xffffffffu, acc, off);
    if (lane == 0) {
        acc += bias[o];
        g_h2[gid] = acc > 0.f ? acc : 0.01f * acc;
    }
}

__global__ void __launch_bounds__(256) fc3_kernel(const float* __restrict__ w,
                                                  const float* __restrict__ bias,
                                                  float* __restrict__ out) {
    const int gid = blockIdx.x * 8 + (threadIdx.x >> 5);
    const int lane = threadIdx.x & 31;
    if (gid >= 8 * 20) return;
    const int b = gid / 20, o = gid % 20;
    const float* wr = w + (size_t)o * 256 + lane * 8;
    const float* xr = g_h2 + b * 256 + lane * 8;
    float4 w0 = *(const float4*)wr,  w1 = *(const float4*)(wr + 4);
    float4 x0 = *(const float4*)xr,  x1 = *(const float4*)(xr + 4);
    float acc = w0.x*x0.x + w0.y*x0.y + w0.z*x0.z + w0.w*x0.w
              + w1.x*x1.x + w1.y*x1.y + w1.z*x1.z + w1.w*x1.w;
    #pragma unroll
    for (int off = 16; off > 0; off >>= 1)
        acc += __shfl_xor_sync(0xffffffffu, acc, off);
    if (lane == 0) out[b * 20 + o] = acc + bias[o];
}

// ======================================================================
extern "C" void kernel_launch(void* const* d_in, const int* in_sizes, int n_in,
                              void* d_out, int out_size) {
    const int*   text = (const int*)d_in[0];
    const float* emb  = (const float*)d_in[1];
    const float* ipw  = (const float*)d_in[2];
    const float* ipb  = (const float*)d_in[3];
    const float* opw  = (const float*)d_in[4];
    const float* opb  = (const float*)d_in[5];
    const float* fc1w = (const float*)d_in[6];
    const float* fc1b = (const float*)d_in[7];
    const float* fc2w = (const float*)d_in[8];
    const float* fc2b = (const float*)d_in[9];
    const float* fc3w = (const float*)d_in[10];
    const float* fc3b = (const float*)d_in[11];
    float* out = (float*)d_out;

    prep_kernel<<<448, 256>>>(text, emb, ipw, opw);

    qkv_gemm<<<dim3(M_TOT / 128, 6), 256>>>(ipb);

    const int attn_smem = (WROWS * KSTR + QT * KSTR + 64 * VSTR
                           + QT * SSTR + QT * PSTR) * sizeof(float);
    cudaFuncSetAttribute(attn_kernel, cudaFuncAttributeMaxDynamicSharedMemorySize, attn_smem);
    attn_kernel<<<B_ * H_ * (S_ / QT), AT_THR, attn_smem>>>();

    proj_pool_gemm<<<dim3(M_TOT / 128, 2), 256>>>(opb);

    fc1_kernel<<<512, 256>>>(fc1w, fc1b);
    fc2_kernel<<<256, 256>>>(fc2w, fc2b);
    fc3_kernel<<<20, 256>>>(fc3w, fc3b, out);
}

// round 14
// speedup vs baseline: 1.2343x; 1.0279x over previous
#include <cuda_runtime.h>
#include <cuda_bf16.h>

#define B_   8
#define S_   2048
#define E_   256
#define H_   4
#define D_   64
#define M_TOT (B_*S_)

// attention tile
#define QT2  32
#define WR2  160
#define KS2  68
#define VS2  161
#define SPS  164
#define AT_THR 512

typedef unsigned long long u64;

#define TF32(o, x) asm("cvt.rna.tf32.f32 %0, %1;" : "=r"(o) : "f"(x))
__device__ __forceinline__ float tf32r(float x) {
    unsigned u; TF32(u, x); return __uint_as_float(u);
}
#define MMA_TF32(c, a, b) \
    asm("mma.sync.aligned.m16n8k8.row.col.f32.tf32.tf32.f32 " \
        "{%0,%1,%2,%3}, {%4,%5,%6,%7}, {%8,%9}, {%0,%1,%2,%3};" \
        : "+f"((c).x), "+f"((c).y), "+f"((c).z), "+f"((c).w) \
        : "r"((a)[0]), "r"((a)[1]), "r"((a)[2]), "r"((a)[3]), \
          "r"((b)[0]), "r"((b)[1]))

#define ASTR 36

// -------- scratch --------
__device__ float g_x[(size_t)M_TOT * E_];
__device__ float g_wi[768 * 256];
__device__ float g_wo[256 * 256];
__device__ float g_qkv[3ull * B_ * H_ * S_ * D_];
__device__ float g_attn[(size_t)M_TOT * E_];
__device__ unsigned int g_ctx_u[B_ * E_];
__device__ float g_h1[B_ * 512];
__device__ float g_h2[B_ * 256];

__device__ __forceinline__ unsigned int f2ord(float f) {
    unsigned int u = __float_as_uint(f);
    return (u & 0x80000000u) ? ~u : (u | 0x80000000u);
}
__device__ __forceinline__ float ord2f(unsigned int u) {
    return (u & 0x80000000u) ? __uint_as_float(u & 0x7FFFFFFFu)
                             : __uint_as_float(~u);
}

// ======================================================================
// Kernel 0: producer-side rounding + ctx init.
// ======================================================================
#define NX  (M_TOT * 64)
#define NWI (768 * 64)
#define NWO (256 * 64)
__global__ void __launch_bounds__(256) prep_kernel(const int* __restrict__ text,
                                                   const float* __restrict__ emb,
                                                   const float* __restrict__ wi,
                                                   const float* __restrict__ wo) {
    if (blockIdx.x < 8) g_ctx_u[blockIdx.x * 256 + threadIdx.x] = 0u;
    const int total = NX + NWI + NWO;
    for (int i = blockIdx.x * 256 + threadIdx.x; i < total; i += gridDim.x * 256) {
        float4 v; float4* dst;
        if (i < NX) {
            int m = i >> 6, c4 = i & 63;
            v = ((const float4*)emb)[(size_t)text[m] * 64 + c4];
            dst = (float4*)g_x + i;
        } else if (i < NX + NWI) {
            int j = i - NX;
            v = ((const float4*)wi)[j];
            dst = (float4*)g_wi + j;
        } else {
            int j = i - NX - NWI;
            v = ((const float4*)wo)[j];
            dst = (float4*)g_wo + j;
        }
        v.x = tf32r(v.x); v.y = tf32r(v.y); v.z = tf32r(v.z); v.w = tf32r(v.w);
        *dst = v;
    }
}

// ======================================================================
// Kernel 1: QKV GEMM on pre-rounded X/W (R13, unchanged).
// ======================================================================
__global__ void __launch_bounds__(256) qkv_gemm(const float* __restrict__ bias) {
    __shared__ unsigned As[128 * ASTR];
    __shared__ unsigned Ws[128 * ASTR];

    const int tid = threadIdx.x;
    const int wid = tid >> 5, lane = tid & 31;
    const int wm = wid & 3, wn = wid >> 2;
    const int qr = lane >> 2, qc = lane & 3;
    const int m0 = blockIdx.x * 128, n0 = blockIdx.y * 128;

    float4 c[2][8] = {};

    for (int kt = 0; kt < 256; kt += 32) {
        __syncthreads();
        #pragma unroll
        for (int it = 0; it < 4; ++it) {
            int idx = tid + it * 256;
            int row = idx >> 3;
            int c4  = (idx & 7) * 4;
            *(uint4*)&As[row * ASTR + c4] =
                *(const uint4*)&g_x[(size_t)(m0 + row) * 256 + kt + c4];
            *(uint4*)&Ws[row * ASTR + c4] =
                *(const uint4*)&g_wi[(size_t)(n0 + row) * 256 + kt + c4];
        }
        __syncthreads();
        #pragma unroll
        for (int ks = 0; ks < 4; ++ks) {
            const int k0 = ks * 8;
            unsigned a[2][4], b[8][2];
            #pragma unroll
            for (int mt = 0; mt < 2; ++mt) {
                int rb = wm * 32 + mt * 16 + qr;
                a[mt][0] = As[(rb    ) * ASTR + k0 + qc];
                a[mt][1] = As[(rb + 8) * ASTR + k0 + qc];
                a[mt][2] = As[(rb    ) * ASTR + k0 + qc + 4];
                a[mt][3] = As[(rb + 8) * ASTR + k0 + qc + 4];
            }
            #pragma unroll
            for (int nt = 0; nt < 8; ++nt) {
                int nb = wn * 64 + nt * 8 + qr;
                b[nt][0] = Ws[nb * ASTR + k0 + qc];
                b[nt][1] = Ws[nb * ASTR + k0 + qc + 4];
            }
            #pragma unroll
            for (int mt = 0; mt < 2; ++mt)
                #pragma unroll
                for (int nt = 0; nt < 8; ++nt)
                    MMA_TF32(c[mt][nt], a[mt], b[nt]);
        }
    }

    #pragma unroll
    for (int nt = 0; nt < 8; ++nt) {
        const int n_g = n0 + wn * 64 + nt * 8 + 2 * qc;
        const int sec = n_g >> 8;
        const int h   = (n_g >> 6) & 3;
        const int d   = n_g & 63;
        const float scale = (sec == 0) ? 0.125f : 1.0f;
        const float b0v = bias[n_g], b1v = bias[n_g + 1];
        #pragma unroll
        for (int mt = 0; mt < 2; ++mt) {
            float4 cc = c[mt][nt];
            int r = wm * 32 + mt * 16 + qr;
            #pragma unroll
            for (int half = 0; half < 2; ++half) {
                int m = m0 + r + half * 8;
                int bb = m >> 11, s = m & 2047;
                float2 o;
                o.x = tf32r(((half ? cc.z : cc.x) + b0v) * scale);
                o.y = tf32r(((half ? cc.w : cc.y) + b1v) * scale);
                *(float2*)&g_qkv[((((size_t)sec * B_ + bb) * H_ + h) * S_ + s) * 64 + d] = o;
            }
        }
    }
}

// ======================================================================
// Kernel 2: banded attention, QT=32, 512 threads, P aliases S.
// Pre-rounded staging (no cvt). smem = 114432 B -> 2 blocks/SM.
// ======================================================================
__global__ void __launch_bounds__(AT_THR) attn_kernel() {
    extern __shared__ float smem[];
    float* K_s = smem;                  // [160][68]
    float* Q_s = K_s + WR2 * KS2;       // [32][68]
    float* V_s = Q_s + QT2 * KS2;       // [64][161]
    float* S_s = V_s + 64 * VS2;        // [32][164]  (P aliases)
    unsigned* Ku = (unsigned*)K_s;
    unsigned* Qu = (unsigned*)Q_s;
    unsigned* Vu = (unsigned*)V_s;
    unsigned* Pu = (unsigned*)S_s;

    const int nq = S_ / QT2;            // 64
    const int qt = blockIdx.x % nq;
    const int h  = (blockIdx.x / nq) % H_;
    const int b  = blockIdx.x / (nq * H_);

    const int q0 = qt * QT2;
    const int kstart = q0 - 64;

    const float* qb = g_qkv + ((size_t)(b * H_ + h)) * S_ * 64;
    const float* kb = g_qkv + ((size_t)(B_ * H_) + b * H_ + h) * S_ * 64;
    const float* vb = g_qkv + ((size_t)(2 * B_ * H_) + b * H_ + h) * S_ * 64;

    const int tid = threadIdx.x;
    const int wid = tid >> 5, lane = tid & 31;
    const int qr = lane >> 2, qc = lane & 3;

    // ---- stage K and V^T (raw pre-rounded bits) ----
    for (int idx = tid; idx < WR2 * 16; idx += AT_THR) {
        int row = idx >> 4, d4 = (idx & 15) * 4;
        int kg = kstart + row;
        bool in = (kg >= 0) && (kg < S_);
        float4 kv = in ? *(const float4*)&kb[(size_t)kg * 64 + d4]
                       : make_float4(0.f,0.f,0.f,0.f);
        *(float4*)&K_s[row * KS2 + d4] = kv;
        float4 vv = in ? *(const float4*)&vb[(size_t)kg * 64 + d4]
                       : make_float4(0.f,0.f,0.f,0.f);
        V_s[(d4+0) * VS2 + row] = vv.x;
        V_s[(d4+1) * VS2 + row] = vv.y;
        V_s[(d4+2) * VS2 + row] = vv.z;
        V_s[(d4+3) * VS2 + row] = vv.w;
    }
    // ---- stage Q: exactly 512 items ----
    {
        int r = tid >> 4, d4 = (tid & 15) * 4;
        *(float4*)&Q_s[r * KS2 + d4] = *(const float4*)&qb[(size_t)(q0 + r) * 64 + d4];
    }
    __syncthreads();

    // ---- scores: S[32,160] = Q x K^T. 40 units over 16 warps ----
    for (int u = wid; u < 40; u += 16) {
        const int mt = u / 20, tt = u % 20;
        float4 c = {0.f, 0.f, 0.f, 0.f};
        #pragma unroll
        for (int ks = 0; ks < 8; ++ks) {
            const int k0 = ks * 8;
            unsigned a[4], bf[2];
            a[0] = Qu[(mt * 16 + qr    ) * KS2 + k0 + qc];
            a[1] = Qu[(mt * 16 + qr + 8) * KS2 + k0 + qc];
            a[2] = Qu[(mt * 16 + qr    ) * KS2 + k0 + qc + 4];
            a[3] = Qu[(mt * 16 + qr + 8) * KS2 + k0 + qc + 4];
            bf[0] = Ku[(tt * 8 + qr) * KS2 + k0 + qc];
            bf[1] = Ku[(tt * 8 + qr) * KS2 + k0 + qc + 4];
            MMA_TF32(c, a, bf);
        }
        *(float2*)&S_s[(mt * 16 + qr    ) * SPS + tt * 8 + 2 * qc] = make_float2(c.x, c.y);
        *(float2*)&S_s[(mt * 16 + qr + 8) * SPS + tt * 8 + 2 * qc] = make_float2(c.z, c.w);
    }
    __syncthreads();

    // ---- softmax: warp handles rows 2*wid, 2*wid+1; P overwrites S ----
    #pragma unroll
    for (int rr = 0; rr < 2; ++rr) {
        const int row = wid * 2 + rr;
        float sc[5];
        #pragma unroll
        for (int r = 0; r < 5; ++r) {
            int t = lane + 32 * r;
            int j = row + t;
            int kg = kstart + j;
            bool valid = (t <= 128) && (kg >= 0) && (kg < S_);
            sc[r] = valid ? S_s[row * SPS + j] : -3.0e38f;
        }
        float mx = sc[0];
        #pragma unroll
        for (int r = 1; r < 5; ++r) mx = fmaxf(mx, sc[r]);
        #pragma unroll
        for (int off = 16; off > 0; off >>= 1)
            mx = fmaxf(mx, __shfl_xor_sync(0xffffffffu, mx, off));
        float sum = 0.f;
        #pragma unroll
        for (int r = 0; r < 5; ++r) { sc[r] = __expf(sc[r] - mx); sum += sc[r]; }
        #pragma unroll
        for (int off = 16; off > 0; off >>= 1)
            sum += __shfl_xor_sync(0xffffffffu, sum, off);
        float inv = 1.0f / sum;

        #pragma unroll
        for (int t = lane; t < WR2; t += 32) Pu[row * SPS + t] = 0u;
        __syncwarp();
        #pragma unroll
        for (int r = 0; r < 5; ++r) {
            int t = lane + 32 * r;
            if (t <= 128) {
                float p = sc[r] * inv;
                unsigned u; TF32(u, p);
                Pu[row * SPS + row + t] = u;
            }
        }
        __syncwarp();
    }
    __syncthreads();

    // ---- AV: D[32,64] = P x V. 16 units: warp = (mt, nt), 20 k-steps ----
    {
        const int mt = wid >> 3, nt = wid & 7;
        float4 d = {0.f, 0.f, 0.f, 0.f};
        #pragma unroll
        for (int ks = 0; ks < 20; ++ks) {
            const int k0 = ks * 8;
            unsigned a[4], bf[2];
            a[0] = Pu[(mt * 16 + qr    ) * SPS + k0 + qc];
            a[1] = Pu[(mt * 16 + qr + 8) * SPS + k0 + qc];
            a[2] = Pu[(mt * 16 + qr    ) * SPS + k0 + qc + 4];
            a[3] = Pu[(mt * 16 + qr + 8) * SPS + k0 + qc + 4];
            bf[0] = Vu[(nt * 8 + qr) * VS2 + k0 + qc];
            bf[1] = Vu[(nt * 8 + qr) * VS2 + k0 + qc + 4];
            MMA_TF32(d, a, bf);
        }
        const int dim = h * 64 + nt * 8 + 2 * qc;
        int s = q0 + mt * 16 + qr;
        *(float2*)&g_attn[((size_t)(b * S_ + s)) * 256 + dim] =
            make_float2(tf32r(d.x), tf32r(d.y));
        s += 8;
        *(float2*)&g_attn[((size_t)(b * S_ + s)) * 256 + dim] =
            make_float2(tf32r(d.z), tf32r(d.w));
    }
}

// ======================================================================
// Kernel 3: out_proj GEMM + fused max-pool (R13, unchanged).
// ======================================================================
__global__ void __launch_bounds__(256) proj_pool_gemm(const float* __restrict__ bias) {
    __shared__ unsigned As[128 * ASTR];
    __shared__ unsigned Ws[128 * ASTR];

    const int tid = threadIdx.x;
    const int wid = tid >> 5, lane = tid & 31;
    const int wm = wid & 3, wn = wid >> 2;
    const int qr = lane >> 2, qc = lane & 3;
    const int m0 = blockIdx.x * 128, n0 = blockIdx.y * 128;

    float4 c[2][8] = {};

    for (int kt = 0; kt < 256; kt += 32) {
        __syncthreads();
        #pragma unroll
        for (int it = 0; it < 4; ++it) {
            int idx = tid + it * 256;
            int row = idx >> 3;
            int c4  = (idx & 7) * 4;
            *(uint4*)&As[row * ASTR + c4] =
                *(const uint4*)&g_attn[(size_t)(m0 + row) * 256 + kt + c4];
            *(uint4*)&Ws[row * ASTR + c4] =
                *(const uint4*)&g_wo[(size_t)(n0 + row) * 256 + kt + c4];
        }
        __syncthreads();
        #pragma unroll
        for (int ks = 0; ks < 4; ++ks) {
            const int k0 = ks * 8;
            unsigned a[2][4], b[8][2];
            #pragma unroll
            for (int mt = 0; mt < 2; ++mt) {
                int rb = wm * 32 + mt * 16 + qr;
                a[mt][0] = As[(rb    ) * ASTR + k0 + qc];
                a[mt][1] = As[(rb + 8) * ASTR + k0 + qc];
                a[mt][2] = As[(rb    ) * ASTR + k0 + qc + 4];
                a[mt][3] = As[(rb + 8) * ASTR + k0 + qc + 4];
            }
            #pragma unroll
            for (int nt = 0; nt < 8; ++nt) {
                int nb = wn * 64 + nt * 8 + qr;
                b[nt][0] = Ws[nb * ASTR + k0 + qc];
                b[nt][1] = Ws[nb * ASTR + k0 + qc + 4];
            }
            #pragma unroll
            for (int mt = 0; mt < 2; ++mt)
                #pragma unroll
                for (int nt = 0; nt < 8; ++nt)
                    MMA_TF32(c[mt][nt], a[mt], b[nt]);
        }
    }

    float v0[8], v1[8];
    #pragma unroll
    for (int nt = 0; nt < 8; ++nt) {
        v0[nt] = fmaxf(fmaxf(c[0][nt].x, c[0][nt].z), fmaxf(c[1][nt].x, c[1][nt].z));
        v1[nt] = fmaxf(fmaxf(c[0][nt].y, c[0][nt].w), fmaxf(c[1][nt].y, c[1][nt].w));
    }
    #pragma unroll
    for (int off = 4; off <= 16; off <<= 1) {
        #pragma unroll
        for (int nt = 0; nt < 8; ++nt) {
            v0[nt] = fmaxf(v0[nt], __shfl_xor_sync(0xffffffffu, v0[nt], off));
            v1[nt] = fmaxf(v1[nt], __shfl_xor_sync(0xffffffffu, v1[nt], off));
        }
    }
    if (lane < 4) {
        const int bb = m0 >> 11;
        #pragma unroll
        for (int nt = 0; nt < 8; ++nt) {
            int n_g = n0 + wn * 64 + nt * 8 + 2 * lane;
            atomicMax(&g_ctx_u[bb * 256 + n_g],     f2ord(v0[nt] + bias[n_g]));
            atomicMax(&g_ctx_u[bb * 256 + n_g + 1], f2ord(v1[nt] + bias[n_g + 1]));
        }
    }
}

// ======================================================================
// MLP head.
// ======================================================================
__global__ void __launch_bounds__(256) fc1_kernel(const float* __restrict__ w,
                                                  const float* __restrict__ bias) {
    const int gid = blockIdx.x * 8 + (threadIdx.x >> 5);
    const int lane = threadIdx.x & 31;
    const int b = gid >> 9, o = gid & 511;
    const float* wr = w + (size_t)o * 256 + lane * 8;
    const unsigned* xr = g_ctx_u + b * 256 + lane * 8;
    float4 w0 = *(const float4*)wr,  w1 = *(const float4*)(wr + 4);
    uint4 xu0 = *(const uint4*)xr,   xu1 = *(const uint4*)(xr + 4);
    float acc = w0.x*ord2f(xu0.x) + w0.y*ord2f(xu0.y) + w0.z*ord2f(xu0.z) + w0.w*ord2f(xu0.w)
              + w1.x*ord2f(xu1.x) + w1.y*ord2f(xu1.y) + w1.z*ord2f(xu1.z) + w1.w*ord2f(xu1.w);
    #pragma unroll
    for (int off = 16; off > 0; off >>= 1)
        acc += __shfl_xor_sync(0xffffffffu, acc, off);
    if (lane == 0) {
        acc += bias[o];
        g_h1[gid] = acc > 0.f ? acc : 0.01f * acc;
    }
}

__global__ void __launch_bounds__(256) fc2_kernel(const float* __restrict__ w,
                                                  const float* __restrict__ bias) {
    const int gid = blockIdx.x * 8 + (threadIdx.x >> 5);
    const int lane = threadIdx.x & 31;
    const int b = gid >> 8, o = gid & 255;
    const float* wr = w + (size_t)o * 512 + lane * 16;
    const float* xr = g_h1 + b * 512 + lane * 16;
    float acc = 0.f;
    #pragma unroll
    for (int cc = 0; cc < 4; ++cc) {
        float4 wv = *(const float4*)(wr + cc * 4);
        float4 xv = *(const float4*)(xr + cc * 4);
        acc += wv.x*xv.x + wv.y*xv.y + wv.z*xv.z + wv.w*xv.w;
    }
    #pragma unroll
    for (int off = 16; off > 0; off >>= 1)
        acc += __shfl_xor_sync(0xffffffffu, acc, off);
    if (lane == 0) {
        acc += bias[o];
        g_h2[gid] = acc > 0.f ? acc : 0.01f * acc;
    }
}

__global__ void __launch_bounds__(256) fc3_kernel(const float* __restrict__ w,
                                                  const float* __restrict__ bias,
                                                  float* __restrict__ out) {
    const int gid = blockIdx.x * 8 + (threadIdx.x >> 5);
    const int lane = threadIdx.x & 31;
    if (gid >= 8 * 20) return;
    const int b = gid / 20, o = gid % 20;
    const float* wr = w + (size_t)o * 256 + lane * 8;
    const float* xr = g_h2 + b * 256 + lane * 8;
    float4 w0 = *(const float4*)wr,  w1 = *(const float4*)(wr + 4);
    float4 x0 = *(const float4*)xr,  x1 = *(const float4*)(xr + 4);
    float acc = w0.x*x0.x + w0.y*x0.y + w0.z*x0.z + w0.w*x0.w
              + w1.x*x1.x + w1.y*x1.y + w1.z*x1.z + w1.w*x1.w;
    #pragma unroll
    for (int off = 16; off > 0; off >>= 1)
        acc += __shfl_xor_sync(0xffffffffu, acc, off);
    if (lane == 0) out[b * 20 + o] = acc + bias[o];
}

// ======================================================================
extern "C" void kernel_launch(void* const* d_in, const int* in_sizes, int n_in,
                              void* d_out, int out_size) {
    const int*   text = (const int*)d_in[0];
    const float* emb  = (const float*)d_in[1];
    const float* ipw  = (const float*)d_in[2];
    const float* ipb  = (const float*)d_in[3];
    const float* opw  = (const float*)d_in[4];
    const float* opb  = (const float*)d_in[5];
    const float* fc1w = (const float*)d_in[6];
    const float* fc1b = (const float*)d_in[7];
    const float* fc2w = (const float*)d_in[8];
    const float* fc2b = (const float*)d_in[9];
    const float* fc3w = (const float*)d_in[10];
    const float* fc3b = (const float*)d_in[11];
    float* out = (float*)d_out;

    prep_kernel<<<448, 256>>>(text, emb, ipw, opw);

    qkv_gemm<<<dim3(M_TOT / 128, 6), 256>>>(ipb);

    const int attn_smem = (WR2 * KS2 + QT2 * KS2 + 64 * VS2 + QT2 * SPS) * sizeof(float); // 114432
    cudaFuncSetAttribute(attn_kernel, cudaFuncAttributeMaxDynamicSharedMemorySize, attn_smem);
    attn_kernel<<<B_ * H_ * (S_ / QT2), AT_THR, attn_smem>>>();

    proj_pool_gemm<<<dim3(M_TOT / 128, 2), 256>>>(opb);

    fc1_kernel<<<512, 256>>>(fc1w, fc1b);
    fc2_kernel<<<256, 256>>>(fc2w, fc2b);
    fc3_kernel<<<20, 256>>>(fc3w, fc3b, out);
}